// round 9
// baseline (speedup 1.0000x reference)
#include <cuda_runtime.h>
#include <math.h>
#include <stdint.h>

#define QN 2048
#define NPTS 32768
#define DM 256
#define KNN 8
#define NH 8
#define HDIM 64
#define STATE 64
#define DINN 512
#define CONVN 640
#define NPROJN 1160
#define HIDN 1024
#define CSZ 64
#define NCH 32

// ---------------- scratch ----------------
__device__ float g_q[QN*DM];
__device__ float g_fbar[QN*DM];
__device__ float g_vbar[QN*DM];
__device__ float g_x[QN*DM];
__device__ float g_tmp[QN*DM];
__device__ int   g_idx[QN*KNN];
__device__ int   g_inv[2*QN];
__device__ float g_xs[2*QN*DM];
__device__ float g_proj[2*QN*NPROJN];
__device__ float g_xbc[2*QN*CONVN];
__device__ float g_dts[2*QN*NH];
__device__ float g_Las[2*QN*NH];
__device__ float g_Hc[2*NH*NCH*HDIM*STATE];
__device__ float g_Hin[2*NH*NCH*HDIM*STATE];
__device__ float g_y[2*QN*DINN];
__device__ float g_gated[2*QN*DINN];
__device__ float g_ssmout[2*QN*DM];
__device__ float g_ffnh[QN*HIDN];

__device__ __forceinline__ float sigmoidf_(float x){ return 1.f/(1.f+expf(-x)); }
__device__ __forceinline__ float warpSum(float v){
  #pragma unroll
  for (int o=16;o;o>>=1) v += __shfl_xor_sync(0xffffffffu, v, o);
  return v;
}
__device__ __forceinline__ void mma_tf32(float* d, uint32_t a0,uint32_t a1,uint32_t a2,uint32_t a3,
                                         uint32_t b0,uint32_t b1){
  asm volatile(
    "mma.sync.aligned.m16n8k8.row.col.f32.tf32.tf32.f32 "
    "{%0,%1,%2,%3}, {%4,%5,%6,%7}, {%8,%9}, {%0,%1,%2,%3};"
    : "+f"(d[0]),"+f"(d[1]),"+f"(d[2]),"+f"(d[3])
    : "r"(a0),"r"(a1),"r"(a2),"r"(a3),"r"(b0),"r"(b1));
}
__device__ __forceinline__ void cpa16(uint32_t s, const float* g, bool v){
  int sz = v?16:0;
  asm volatile("cp.async.cg.shared.global [%0], [%1], 16, %2;" :: "r"(s), "l"(g), "r"(sz));
}

// ---------------- KNN ----------------
#define TPTS 2048
__global__ void knn_kernel(const float* __restrict__ qpos, const float* __restrict__ spos){
  __shared__ float sp[TPTS*3];
  int warp = threadIdx.x>>5, lane = threadIdx.x&31;
  int q = blockIdx.x*8 + warp;
  float qx=qpos[q*3+0], qy=qpos[q*3+1], qz=qpos[q*3+2];
  float qq = qx*qx+qy*qy+qz*qz;
  float bd[8]; int bi[8];
  #pragma unroll
  for (int j=0;j<8;j++){ bd[j]=3.0e38f; bi[j]=0x7fffffff; }
  for (int tile=0;tile<NPTS/TPTS;tile++){
    __syncthreads();
    for (int i=threadIdx.x;i<TPTS*3;i+=256) sp[i]=spos[tile*TPTS*3+i];
    __syncthreads();
    for (int p=lane;p<TPTS;p+=32){
      float sx=sp[3*p], sy=sp[3*p+1], sz=sp[3*p+2];
      float ss = sx*sx+sy*sy+sz*sz;
      float dot = qx*sx+qy*sy+qz*sz;
      float d2 = qq + ss - 2.f*dot;
      if (d2 < bd[7]){
        bd[7]=d2; bi[7]=tile*TPTS+p;
        for (int j=7;j>0;j--){
          if (bd[j]<bd[j-1]){ float td=bd[j];bd[j]=bd[j-1];bd[j-1]=td;
                              int ti=bi[j];bi[j]=bi[j-1];bi[j-1]=ti; }
          else break;
        }
      }
    }
  }
  for (int off=16;off;off>>=1){
    float od[8]; int oi[8];
    #pragma unroll
    for (int j=0;j<8;j++){
      od[j]=__shfl_xor_sync(0xffffffffu,bd[j],off);
      oi[j]=__shfl_xor_sync(0xffffffffu,bi[j],off);
    }
    float nd[8]; int ni[8]; int a=0,c=0;
    for (int t=0;t<8;t++){
      bool mine;
      if (a>=8) mine=false;
      else if (c>=8) mine=true;
      else mine = (bd[a]<od[c]) || (bd[a]==od[c] && bi[a]<=oi[c]);
      if (mine){ nd[t]=bd[a];ni[t]=bi[a];a++; } else { nd[t]=od[c];ni[t]=oi[c];c++; }
    }
    for (int j=0;j<8;j++){ bd[j]=nd[j]; bi[j]=ni[j]; }
  }
  if (lane==0){
    #pragma unroll
    for (int j=0;j<8;j++) g_idx[q*8+j]=bi[j];
  }
}

__global__ void inv_kernel(const int* __restrict__ order){
  int id=blockIdx.x*blockDim.x+threadIdx.x;
  if (id<2*QN) g_inv[(id/QN)*QN + order[id]] = id%QN;
}

// ---------------- tf32 GEMM, cp.async 3-stage ----------------
template<int TBM_, int TBN_, int WM, int WN, int NTHR>
__global__ void __launch_bounds__(NTHR) tgemm_kernel(
    const float* __restrict__ A, const float* __restrict__ B,
    const float* __restrict__ bias, const float* __restrict__ emul,
    float* __restrict__ Cmat, int M, int Nn, int Kk, int act){
  constexpr int S=3;
  constexpr int MW = TBM_/WM;
  constexpr int MI = WM/16, NI = WN/8;
  constexpr int ROWS = TBM_+TBN_;
  constexpr int SLOTS = ROWS*4;
  constexpr int CNT = (SLOTS+NTHR-1)/NTHR;
  __shared__ float Sm[S][ROWS][20];
  int tid=threadIdx.x, warp=tid>>5, lane=tid&31;
  int wm=(warp%MW)*WM, wn=(warp/MW)*WN;
  int g=lane>>2, tig=lane&3;
  int row0=blockIdx.y*TBM_, col0=blockIdx.x*TBN_;

  float acc[MI][NI][4];
  #pragma unroll
  for (int mi=0;mi<MI;mi++)
    #pragma unroll
    for (int ni=0;ni<NI;ni++)
      #pragma unroll
      for (int r=0;r<4;r++) acc[mi][ni][r]=0.f;

  const float* gp[CNT]; uint32_t so[CNT]; bool val[CNT]; bool actv[CNT];
  #pragma unroll
  for (int i=0;i<CNT;i++){
    int idx=tid+i*NTHR;
    actv[i]=(idx<SLOTS);
    int idc = actv[i]? idx : 0;
    int r=idc>>2, c=(idc&3)<<2;
    if (r<TBM_){ gp[i]=A+(size_t)(row0+r)*Kk+c; val[i]=true; }
    else { int rb=r-TBM_; gp[i]=B+(size_t)(col0+rb)*Kk+c; val[i]=(col0+rb)<Nn; }
    so[i]=(uint32_t)__cvta_generic_to_shared(&Sm[0][r][c]);
  }
  constexpr uint32_t STGB=ROWS*20*4;
  auto issue=[&](int stage, int k0){
    #pragma unroll
    for (int i=0;i<CNT;i++)
      if (actv[i]) cpa16(so[i]+stage*STGB, gp[i]+k0, val[i]);
  };

  int KT=Kk>>4;
  issue(0,0);  asm volatile("cp.async.commit_group;" ::: "memory");
  issue(1,16); asm volatile("cp.async.commit_group;" ::: "memory");

  int stage=0;
  for (int kt=0;kt<KT;kt++){
    asm volatile("cp.async.wait_group 1;" ::: "memory");
    __syncthreads();
    int nt=kt+S-1;
    if (nt<KT) issue(nt%S, nt<<4);
    asm volatile("cp.async.commit_group;" ::: "memory");
    int p=stage;
    #pragma unroll
    for (int ks=0;ks<16;ks+=8){
      uint32_t af[MI][4], bf[NI][2];
      #pragma unroll
      for (int mi=0;mi<MI;mi++){
        int m=wm+mi*16+g;
        af[mi][0]=__float_as_uint(Sm[p][m  ][ks+tig  ]);
        af[mi][1]=__float_as_uint(Sm[p][m+8][ks+tig  ]);
        af[mi][2]=__float_as_uint(Sm[p][m  ][ks+tig+4]);
        af[mi][3]=__float_as_uint(Sm[p][m+8][ks+tig+4]);
      }
      #pragma unroll
      for (int ni=0;ni<NI;ni++){
        int n=TBM_+wn+ni*8+g;
        bf[ni][0]=__float_as_uint(Sm[p][n][ks+tig  ]);
        bf[ni][1]=__float_as_uint(Sm[p][n][ks+tig+4]);
      }
      #pragma unroll
      for (int mi=0;mi<MI;mi++)
        #pragma unroll
        for (int ni=0;ni<NI;ni++)
          mma_tf32(acc[mi][ni], af[mi][0],af[mi][1],af[mi][2],af[mi][3],
                   bf[ni][0],bf[ni][1]);
    }
    stage = (stage+1==S)? 0 : stage+1;
  }
  #pragma unroll
  for (int mi=0;mi<MI;mi++){
    int r=row0+wm+mi*16+g;
    #pragma unroll
    for (int ni=0;ni<NI;ni++){
      int c=col0+wn+ni*8+2*tig;
      if (c+1<Nn){
        #pragma unroll
        for (int half=0;half<2;half++){
          int rr=r+half*8;
          float v0=acc[mi][ni][half*2+0], v1=acc[mi][ni][half*2+1];
          if (emul){ v0*=emul[(size_t)rr*Nn+c]; v1*=emul[(size_t)rr*Nn+c+1]; }
          if (bias){ v0+=bias[c]; v1+=bias[c+1]; }
          if (act==1){
            v0=0.5f*v0*(1.f+erff(v0*0.70710678118654752f));
            v1=0.5f*v1*(1.f+erff(v1*0.70710678118654752f));
          }
          *(float2*)&Cmat[(size_t)rr*Nn+c]=make_float2(v0,v1);
        }
      }
    }
  }
}

// ---------------- mixbar: warp per query ----------------
__global__ void mixbar2_kernel(const float* __restrict__ wk, const float* __restrict__ wb,
                               const float* __restrict__ feats){
  int warp=threadIdx.x>>5, lane=threadIdx.x&31;
  int q=blockIdx.x*8+warp;
  const float4* q4=(const float4*)g_q;
  float4 qa=q4[q*64+lane], qb=q4[q*64+32+lane];
  const float4* w4=(const float4*)wk;
  float logit[8];
  #pragma unroll
  for (int k=0;k<8;k++){
    float4 wa=w4[k*64+lane], wb4=w4[k*64+32+lane];
    float p=qa.x*wa.x+qa.y*wa.y+qa.z*wa.z+qa.w*wa.w
           +qb.x*wb4.x+qb.y*wb4.y+qb.z*wb4.z+qb.w*wb4.w;
    logit[k]=warpSum(p)+wb[k];
  }
  float m=logit[0];
  #pragma unroll
  for (int k=1;k<8;k++) m=fmaxf(m,logit[k]);
  float s=0.f; float kw[8];
  #pragma unroll
  for (int k=0;k<8;k++){ kw[k]=expf(logit[k]-m); s+=kw[k]; }
  float inv=1.f/s;
  const float4* f4=(const float4*)feats;
  float4 acc0=make_float4(0,0,0,0), acc1=make_float4(0,0,0,0);
  #pragma unroll
  for (int k=0;k<8;k++){
    float w=kw[k]*inv;
    int idx=g_idx[q*8+k];
    float4 fa=f4[(size_t)idx*64+lane], fb=f4[(size_t)idx*64+32+lane];
    acc0.x+=w*fa.x; acc0.y+=w*fa.y; acc0.z+=w*fa.z; acc0.w+=w*fa.w;
    acc1.x+=w*fb.x; acc1.y+=w*fb.y; acc1.z+=w*fb.z; acc1.w+=w*fb.w;
  }
  float4* o4=(float4*)g_fbar;
  o4[q*64+lane]=acc0; o4[q*64+32+lane]=acc1;
}

// ---------------- warp-per-row LayerNorm: out = LN(a + b) ----------------
__global__ void lnw_kernel(float* __restrict__ out, const float* __restrict__ a,
                           const float* __restrict__ b){
  int row=blockIdx.x*8 + (threadIdx.x>>5), lane=threadIdx.x&31;
  const float4* a4=(const float4*)a; const float4* b4=(const float4*)b;
  float4 v0=a4[row*64+lane], v1=a4[row*64+32+lane];
  float4 w0=b4[row*64+lane], w1=b4[row*64+32+lane];
  v0.x+=w0.x;v0.y+=w0.y;v0.z+=w0.z;v0.w+=w0.w;
  v1.x+=w1.x;v1.y+=w1.y;v1.z+=w1.z;v1.w+=w1.w;
  float s=warpSum(v0.x+v0.y+v0.z+v0.w+v1.x+v1.y+v1.z+v1.w);
  float mean=s*(1.f/DM);
  float d0x=v0.x-mean,d0y=v0.y-mean,d0z=v0.z-mean,d0w=v0.w-mean;
  float d1x=v1.x-mean,d1y=v1.y-mean,d1z=v1.z-mean,d1w=v1.w-mean;
  float vs=warpSum(d0x*d0x+d0y*d0y+d0z*d0z+d0w*d0w+d1x*d1x+d1y*d1y+d1z*d1z+d1w*d1w);
  float r=rsqrtf(vs*(1.f/DM)+1e-5f);
  float4* o4=(float4*)out;
  o4[row*64+lane]   =make_float4(d0x*r,d0y*r,d0z*r,d0w*r);
  o4[row*64+32+lane]=make_float4(d1x*r,d1y*r,d1z*r,d1w*r);
}

// ---------------- warp-per-row LN + serialize ----------------
__global__ void lnserw_kernel(const int* __restrict__ order){
  int row=blockIdx.x*8 + (threadIdx.x>>5), lane=threadIdx.x&31;
  int src=order[row];
  const float4* a4=(const float4*)g_x;
  float4 v0=a4[src*64+lane], v1=a4[src*64+32+lane];
  float s=warpSum(v0.x+v0.y+v0.z+v0.w+v1.x+v1.y+v1.z+v1.w);
  float mean=s*(1.f/DM);
  float d0x=v0.x-mean,d0y=v0.y-mean,d0z=v0.z-mean,d0w=v0.w-mean;
  float d1x=v1.x-mean,d1y=v1.y-mean,d1z=v1.z-mean,d1w=v1.w-mean;
  float vs=warpSum(d0x*d0x+d0y*d0y+d0z*d0z+d0w*d0w+d1x*d1x+d1y*d1y+d1z*d1z+d1w*d1w);
  float r=rsqrtf(vs*(1.f/DM)+1e-5f);
  float4* o4=(float4*)g_xs;
  o4[row*64+lane]   =make_float4(d0x*r,d0y*r,d0z*r,d0w*r);
  o4[row*64+32+lane]=make_float4(d1x*r,d1y*r,d1z*r,d1w*r);
}

// ---------------- conv + silu: thread = (b, c4, 8 timesteps) ----------------
__global__ void conv8_kernel(const float* __restrict__ wconv, const float* __restrict__ bconv){
  int id=blockIdx.x*blockDim.x+threadIdx.x;
  int c4=id%160; int t8=(id/160)%(QN/8); int b=id/(160*(QN/8));
  int t0=t8*8;
  const float4* bc4=(const float4*)bconv;
  float4 bias=bc4[c4];
  const float4* w4=(const float4*)wconv;
  float4 w0=w4[c4*4+0], w1=w4[c4*4+1], w2=w4[c4*4+2], w3=w4[c4*4+3];
  const float4* p4=(const float4*)g_proj;
  float4 xv[11];
  #pragma unroll
  for (int i=0;i<11;i++){
    int tt=t0-3+i;
    xv[i] = (tt>=0)? p4[(size_t)(b*QN+tt)*(NPROJN/4) + DINN/4 + c4]
                   : make_float4(0.f,0.f,0.f,0.f);
  }
  float4* ob=(float4*)g_xbc;
  #pragma unroll
  for (int u=0;u<8;u++){
    float4 acc=bias;
    #pragma unroll
    for (int j=0;j<4;j++){
      float4 x=xv[u+j];
      acc.x+=x.x*(&w0.x)[j]; acc.y+=x.y*(&w1.x)[j];
      acc.z+=x.z*(&w2.x)[j]; acc.w+=x.w*(&w3.x)[j];
    }
    acc.x*=sigmoidf_(acc.x); acc.y*=sigmoidf_(acc.y);
    acc.z*=sigmoidf_(acc.z); acc.w*=sigmoidf_(acc.w);
    ob[(size_t)(b*QN+t0+u)*160 + c4]=acc;
  }
}

// ---------------- chunkH: transposed smem, float4 inner loop ----------------
__global__ void chunkH_kernel(const float* __restrict__ alog, const float* __restrict__ dtb){
  __shared__ float Xt[HDIM][CSZ+4];    // Xt[hd][s]
  __shared__ float Bwt[STATE][CSZ+4];  // Bwt[st][s]
  __shared__ float La[CSZ], wv[CSZ];
  int bid=blockIdx.x;
  int c=bid%NCH, h=(bid/NCH)%NH, b=bid/(NCH*NH);
  int tid=threadIdx.x;
  int r0=b*QN + c*CSZ;
  float dtloc=0.f;
  if (tid<CSZ){
    int row=r0+tid;
    float raw = g_proj[(size_t)row*NPROJN + DINN+CONVN + h] + dtb[h];
    dtloc = raw>20.f? raw : log1pf(expf(raw));
    g_dts[row*NH+h]=dtloc;
    float A=-expf(alog[h]);
    La[tid]=dtloc*A;
  }
  __syncthreads();
  for (int o=1;o<CSZ;o<<=1){
    float v=0.f;
    if (tid<CSZ && tid>=o) v=La[tid-o];
    __syncthreads();
    if (tid<CSZ) La[tid]+=v;
    __syncthreads();
  }
  if (tid<CSZ) g_Las[(r0+tid)*NH+h]=La[tid];
  __syncthreads();
  if (tid<CSZ) wv[tid]=expf(La[CSZ-1]-La[tid])*dtloc;
  __syncthreads();
  for (int i=tid;i<CSZ*STATE;i+=256){
    int s=i>>6, k=i&63;
    const float* xr=&g_xbc[(size_t)(r0+s)*CONVN];
    Xt[k][s]=xr[h*HDIM+k];
    Bwt[k][s]=xr[DINN+k]*wv[s];
  }
  __syncthreads();
  int hb=(tid>>4)<<2, sb=(tid&15)<<2;
  float acc[4][4];
  #pragma unroll
  for (int i=0;i<4;i++){ acc[i][0]=0;acc[i][1]=0;acc[i][2]=0;acc[i][3]=0; }
  for (int s=0;s<CSZ;s+=4){
    float4 xv[4], bv[4];
    #pragma unroll
    for (int i=0;i<4;i++) xv[i]=*(const float4*)&Xt[hb+i][s];
    #pragma unroll
    for (int j=0;j<4;j++) bv[j]=*(const float4*)&Bwt[sb+j][s];
    #pragma unroll
    for (int i=0;i<4;i++)
      #pragma unroll
      for (int j=0;j<4;j++)
        acc[i][j]+=xv[i].x*bv[j].x+xv[i].y*bv[j].y+xv[i].z*bv[j].z+xv[i].w*bv[j].w;
  }
  float* Hg=&g_Hc[(size_t)bid*HDIM*STATE];
  #pragma unroll
  for (int i=0;i<4;i++)
    #pragma unroll
    for (int j=0;j<4;j++)
      Hg[(hb+i)*STATE + sb+j]=acc[i][j];
}

// ---------------- carry: 128 blocks ----------------
__global__ void carry_kernel(){
  int bh=blockIdx.x>>3;
  int off=(blockIdx.x&7)*512 + threadIdx.x;
  int b=bh>>3, h=bh&7;
  size_t base0=(size_t)(bh*NCH)*HDIM*STATE;
  float hr=0.f;
  float nxt=g_Hc[base0+off];
  for (int c=0;c<NCH;c++){
    float Lend=g_Las[(b*QN + c*CSZ + CSZ-1)*NH + h];
    float f=expf(Lend);
    float cur=nxt;
    if (c+1<NCH) nxt=g_Hc[base0+(size_t)(c+1)*HDIM*STATE+off];
    g_Hin[base0+(size_t)c*HDIM*STATE+off]=hr;
    hr=f*hr+cur;
  }
}

// ---------------- fully fused P + y_intra + y_inter, float4 loops ----------------
// Phase1: S1=B[s][k], S2=C[t][k] → Pv (regs)
// Phase2: S1=Hi[hd][k] → y2 = C·Hi^T
// Phase3: S2=P[t][s], S1=Xt[hd][s] → y1 = P·X
__global__ void pyfull_kernel(const float* __restrict__ Dh){
  __shared__ float S1[CSZ][STATE+4];
  __shared__ float S2[CSZ][STATE+4];
  __shared__ float La[CSZ], dtv[CSZ];
  int bid=blockIdx.x;
  int c=bid%NCH, h=(bid/NCH)%NH, b=bid/(NCH*NH);
  int tid=threadIdx.x;
  int r0=b*QN + c*CSZ;
  if (tid<CSZ){ La[tid]=g_Las[(r0+tid)*NH+h]; dtv[tid]=g_dts[(r0+tid)*NH+h]; }
  for (int i=tid;i<CSZ*STATE;i+=256){
    int s=i>>6, st=i&63;
    const float* xr=&g_xbc[(size_t)(r0+s)*CONVN];
    S1[s][st]=xr[DINN+st];         // B
    S2[s][st]=xr[DINN+STATE+st];   // C
  }
  __syncthreads();
  int tb=(tid>>4)<<2, sb=(tid&15)<<2;
  // phase 1: C·B^T over k (float4)
  float acc[4][4];
  #pragma unroll
  for (int i=0;i<4;i++){ acc[i][0]=0;acc[i][1]=0;acc[i][2]=0;acc[i][3]=0; }
  for (int k=0;k<STATE;k+=4){
    float4 cv[4], bv[4];
    #pragma unroll
    for (int i=0;i<4;i++) cv[i]=*(const float4*)&S2[tb+i][k];
    #pragma unroll
    for (int j=0;j<4;j++) bv[j]=*(const float4*)&S1[sb+j][k];
    #pragma unroll
    for (int i=0;i<4;i++)
      #pragma unroll
      for (int j=0;j<4;j++)
        acc[i][j]+=cv[i].x*bv[j].x+cv[i].y*bv[j].y+cv[i].z*bv[j].z+cv[i].w*bv[j].w;
  }
  float Pv[4][4];
  #pragma unroll
  for (int i=0;i<4;i++){
    int t=tb+i;
    #pragma unroll
    for (int j=0;j<4;j++){
      int s=sb+j;
      Pv[i][j]=(s<=t)? expf(La[t]-La[s])*dtv[s]*acc[i][j] : 0.f;
    }
  }
  __syncthreads();
  // phase 2: Hi over S1, y2 = C·Hi^T (float4 over k)
  const float* Hg=&g_Hin[(size_t)bid*HDIM*STATE];
  for (int i=tid;i<HDIM*STATE;i+=256) S1[i>>6][i&63]=Hg[i];
  __syncthreads();
  float y2[4][4];
  #pragma unroll
  for (int i=0;i<4;i++){ y2[i][0]=0;y2[i][1]=0;y2[i][2]=0;y2[i][3]=0; }
  for (int k=0;k<STATE;k+=4){
    float4 cv[4], hv[4];
    #pragma unroll
    for (int i=0;i<4;i++) cv[i]=*(const float4*)&S2[tb+i][k];
    #pragma unroll
    for (int j=0;j<4;j++) hv[j]=*(const float4*)&S1[sb+j][k];
    #pragma unroll
    for (int i=0;i<4;i++)
      #pragma unroll
      for (int j=0;j<4;j++)
        y2[i][j]+=cv[i].x*hv[j].x+cv[i].y*hv[j].y+cv[i].z*hv[j].z+cv[i].w*hv[j].w;
  }
  __syncthreads();
  // phase 3: P over S2 [t][s]; X transposed over S1 as Xt[hd][s]
  #pragma unroll
  for (int i=0;i<4;i++)
    #pragma unroll
    for (int j=0;j<4;j++) S2[tb+i][sb+j]=Pv[i][j];
  for (int i=tid;i<CSZ*HDIM;i+=256){
    int s=i>>6,k=i&63;
    S1[k][s]=g_xbc[(size_t)(r0+s)*CONVN + h*HDIM + k];
  }
  __syncthreads();
  int hb=sb;
  float y1[4][4];
  #pragma unroll
  for (int i=0;i<4;i++){ y1[i][0]=0;y1[i][1]=0;y1[i][2]=0;y1[i][3]=0; }
  for (int s=0;s<CSZ;s+=4){
    float4 pv[4], xv[4];
    #pragma unroll
    for (int i=0;i<4;i++) pv[i]=*(const float4*)&S2[tb+i][s];
    #pragma unroll
    for (int j=0;j<4;j++) xv[j]=*(const float4*)&S1[hb+j][s];
    #pragma unroll
    for (int i=0;i<4;i++)
      #pragma unroll
      for (int j=0;j<4;j++)
        y1[i][j]+=pv[i].x*xv[j].x+pv[i].y*xv[j].y+pv[i].z*xv[j].z+pv[i].w*xv[j].w;
  }
  float dh=Dh[h];
  #pragma unroll
  for (int i=0;i<4;i++){
    int t=tb+i;
    float f=expf(La[t]);
    #pragma unroll
    for (int j=0;j<4;j++)
      g_y[(size_t)(r0+t)*DINN + h*HDIM + hb+j] = y1[i][j] + dh*S1[hb+j][t] + f*y2[i][j];
  }
}

// ---------------- warp-per-row gated RMSNorm over 512 ----------------
__global__ void gate_rmsw_kernel(const float* __restrict__ rmsw){
  int row=blockIdx.x*8 + (threadIdx.x>>5), lane=threadIdx.x&31;
  const float4* y4=(const float4*)g_y;
  const float4* p4=(const float4*)g_proj;
  const float4* w4=(const float4*)rmsw;
  float4 gg[4];
  float ssum=0.f;
  #pragma unroll
  for (int i=0;i<4;i++){
    float4 y=y4[(size_t)row*128 + i*32 + lane];
    float4 z=p4[(size_t)row*(NPROJN/4) + i*32 + lane];
    gg[i].x=y.x*(z.x*sigmoidf_(z.x));
    gg[i].y=y.y*(z.y*sigmoidf_(z.y));
    gg[i].z=y.z*(z.z*sigmoidf_(z.z));
    gg[i].w=y.w*(z.w*sigmoidf_(z.w));
    ssum+=gg[i].x*gg[i].x+gg[i].y*gg[i].y+gg[i].z*gg[i].z+gg[i].w*gg[i].w;
  }
  ssum=warpSum(ssum);
  float r=rsqrtf(ssum*(1.f/DINN)+1e-5f);
  float4* o4=(float4*)g_gated;
  #pragma unroll
  for (int i=0;i<4;i++){
    float4 w=w4[i*32+lane];
    o4[(size_t)row*128 + i*32 + lane]=make_float4(gg[i].x*r*w.x, gg[i].y*r*w.y,
                                                  gg[i].z*r*w.z, gg[i].w*r*w.w);
  }
}

// ---------------- warp-per-row unsort + average + residual + LN ----------------
__global__ void merge_lnw_kernel(){
  int q=blockIdx.x*8 + (threadIdx.x>>5), lane=threadIdx.x&31;
  int i0=g_inv[q], i1=g_inv[QN+q];
  const float4* x4=(const float4*)g_x;
  const float4* s4=(const float4*)g_ssmout;
  float4 v0=x4[q*64+lane], v1=x4[q*64+32+lane];
  float4 a0=s4[(size_t)i0*64+lane], a1=s4[(size_t)i0*64+32+lane];
  float4 b0=s4[(size_t)(QN+i1)*64+lane], b1=s4[(size_t)(QN+i1)*64+32+lane];
  v0.x+=0.5f*(a0.x+b0.x); v0.y+=0.5f*(a0.y+b0.y);
  v0.z+=0.5f*(a0.z+b0.z); v0.w+=0.5f*(a0.w+b0.w);
  v1.x+=0.5f*(a1.x+b1.x); v1.y+=0.5f*(a1.y+b1.y);
  v1.z+=0.5f*(a1.z+b1.z); v1.w+=0.5f*(a1.w+b1.w);
  float s=warpSum(v0.x+v0.y+v0.z+v0.w+v1.x+v1.y+v1.z+v1.w);
  float mean=s*(1.f/DM);
  float d0x=v0.x-mean,d0y=v0.y-mean,d0z=v0.z-mean,d0w=v0.w-mean;
  float d1x=v1.x-mean,d1y=v1.y-mean,d1z=v1.z-mean,d1w=v1.w-mean;
  float vs=warpSum(d0x*d0x+d0y*d0y+d0z*d0z+d0w*d0w+d1x*d1x+d1y*d1y+d1z*d1z+d1w*d1w);
  float r=rsqrtf(vs*(1.f/DM)+1e-5f);
  float4* o4=(float4*)g_x;
  o4[q*64+lane]   =make_float4(d0x*r,d0y*r,d0z*r,d0w*r);
  o4[q*64+32+lane]=make_float4(d1x*r,d1y*r,d1z*r,d1w*r);
}

// =====================================================================
extern "C" void kernel_launch(void* const* d_in, const int* in_sizes, int n_in,
                              void* d_out, int out_size){
  const float* query      = (const float*)d_in[0];
  const float* query_pos  = (const float*)d_in[1];
  const float* inst_feats = (const float*)d_in[2];
  const float* sp_coords  = (const float*)d_in[3];
  const float* w_q  = (const float*)d_in[4];
  const float* w_v  = (const float*)d_in[5];
  const float* w_o  = (const float*)d_in[6];
  const float* w_k  = (const float*)d_in[7];
  const float* w_b  = (const float*)d_in[8];
  const float* Win  = (const float*)d_in[9];
  const float* Wconv= (const float*)d_in[10];
  const float* bconv= (const float*)d_in[11];
  const float* Alog = (const float*)d_in[12];
  const float* Dh   = (const float*)d_in[13];
  const float* dtb  = (const float*)d_in[14];
  const float* rmsw = (const float*)d_in[15];
  const float* Wout = (const float*)d_in[16];
  const float* fw1  = (const float*)d_in[17];
  const float* fb1  = (const float*)d_in[18];
  const float* fw2  = (const float*)d_in[19];
  const float* fb2  = (const float*)d_in[20];
  const int*   order= (const int*)  d_in[21];
  float* out = (float*)d_out;

  float *pq,*pfbar,*pvbar,*ptmp,*px,*pxs,*pproj,*pgated,*pssm,*pffnh;
  cudaGetSymbolAddress((void**)&pq,    g_q);
  cudaGetSymbolAddress((void**)&pfbar, g_fbar);
  cudaGetSymbolAddress((void**)&pvbar, g_vbar);
  cudaGetSymbolAddress((void**)&ptmp,  g_tmp);
  cudaGetSymbolAddress((void**)&px,    g_x);
  cudaGetSymbolAddress((void**)&pxs,   g_xs);
  cudaGetSymbolAddress((void**)&pproj, g_proj);
  cudaGetSymbolAddress((void**)&pgated,g_gated);
  cudaGetSymbolAddress((void**)&pssm,  g_ssmout);
  cudaGetSymbolAddress((void**)&pffnh, g_ffnh);

  auto gridS=[](int m,int n){ return dim3((unsigned)(n/32),(unsigned)(m/64)); };
  auto gridB=[](int m,int n){ return dim3((unsigned)((n+63)/64),(unsigned)(m/128)); };
  auto gridP=[](int m,int n){ return dim3((unsigned)((n+127)/128),(unsigned)(m/128)); };

  // --- stage 1 ---
  knn_kernel<<<QN/8,256>>>(query_pos, sp_coords);
  tgemm_kernel<64,32,16,16,256><<<gridS(QN,DM),256>>>(query, w_q, nullptr, nullptr, pq, QN, DM, DM, 0);
  mixbar2_kernel<<<QN/8,256>>>(w_k, w_b, inst_feats);
  tgemm_kernel<64,32,16,16,256><<<gridS(QN,DM),256>>>(pfbar, w_v, nullptr, pq, pvbar, QN, DM, DM, 0);
  tgemm_kernel<64,32,16,16,256><<<gridS(QN,DM),256>>>(pvbar, w_o, nullptr, nullptr, ptmp, QN, DM, DM, 0);
  lnw_kernel<<<QN/8,256>>>(px, ptmp, query);
  inv_kernel<<<(2*QN+255)/256,256>>>(order);

  // --- stage 2: two Mamba2 layers ---
  for (int l=0;l<2;l++){
    lnserw_kernel<<<2*QN/8,256>>>(order);
    tgemm_kernel<128,128,64,32,256><<<gridP(2*QN,NPROJN),256>>>(pxs,
        Win + (size_t)l*NPROJN*DM, nullptr, nullptr, pproj, 2*QN, NPROJN, DM, 0);
    conv8_kernel<<<(2*(QN/8)*160)/256,256>>>(Wconv + (size_t)l*CONVN*4, bconv + (size_t)l*CONVN);
    chunkH_kernel<<<2*NH*NCH,256>>>(Alog + l*NH, dtb + l*NH);
    carry_kernel<<<2*NH*8,512>>>();
    pyfull_kernel<<<2*NH*NCH,256>>>(Dh + l*NH);
    gate_rmsw_kernel<<<2*QN/8,256>>>(rmsw + (size_t)l*DINN);
    tgemm_kernel<64,32,16,16,256><<<gridS(2*QN,DM),256>>>(pgated,
        Wout + (size_t)l*DM*DINN, nullptr, nullptr, pssm, 2*QN, DM, DINN, 0);
    merge_lnw_kernel<<<QN/8,256>>>();
  }

  // --- stage 3: FFN + final LN ---
  tgemm_kernel<128,64,32,32,256><<<gridB(QN,HIDN),256>>>(px, fw1, fb1, nullptr, pffnh, QN, HIDN, DM, 1);
  tgemm_kernel<64,32,16,16,256><<<gridS(QN,DM),256>>>(pffnh, fw2, fb2, nullptr, ptmp, QN, DM, HIDN, 0);
  lnw_kernel<<<QN/8,256>>>(out, ptmp, px);
}

// round 10
// speedup vs baseline: 1.1577x; 1.1577x over previous
#include <cuda_runtime.h>
#include <math.h>
#include <stdint.h>

#define QN 2048
#define NPTS 32768
#define DM 256
#define KNN 8
#define NH 8
#define HDIM 64
#define STATE 64
#define DINN 512
#define CONVN 640
#define NPROJN 1160
#define HIDN 1024
#define CSZ 64
#define NCH 32

// ---------------- scratch ----------------
__device__ float g_q[QN*DM];
__device__ float g_fbar[QN*DM];
__device__ float g_vbar[QN*DM];
__device__ float g_x[QN*DM];
__device__ float g_tmp[QN*DM];
__device__ int   g_idx[QN*KNN];
__device__ int   g_inv[2*QN];
__device__ float g_xs[2*QN*DM];
__device__ float g_proj[2*QN*NPROJN];
__device__ float g_xbc[2*QN*CONVN];
__device__ float g_dts[2*QN*NH];
__device__ float g_Las[2*QN*NH];
__device__ float g_Hc[2*NH*NCH*HDIM*STATE];
__device__ float g_Hin[2*NH*NCH*HDIM*STATE];
__device__ float g_y[2*QN*DINN];
__device__ float g_gated[2*QN*DINN];
__device__ float g_ssmout[2*QN*DM];
__device__ float g_ffnh[QN*HIDN];

__device__ __forceinline__ float sigmoidf_(float x){ return 1.f/(1.f+expf(-x)); }
__device__ __forceinline__ float warpSum(float v){
  #pragma unroll
  for (int o=16;o;o>>=1) v += __shfl_xor_sync(0xffffffffu, v, o);
  return v;
}
__device__ __forceinline__ void mma_tf32(float* d, uint32_t a0,uint32_t a1,uint32_t a2,uint32_t a3,
                                         uint32_t b0,uint32_t b1){
  asm volatile(
    "mma.sync.aligned.m16n8k8.row.col.f32.tf32.tf32.f32 "
    "{%0,%1,%2,%3}, {%4,%5,%6,%7}, {%8,%9}, {%0,%1,%2,%3};"
    : "+f"(d[0]),"+f"(d[1]),"+f"(d[2]),"+f"(d[3])
    : "r"(a0),"r"(a1),"r"(a2),"r"(a3),"r"(b0),"r"(b1));
}
__device__ __forceinline__ void cpa16(uint32_t s, const float* g, bool v){
  int sz = v?16:0;
  asm volatile("cp.async.cg.shared.global [%0], [%1], 16, %2;" :: "r"(s), "l"(g), "r"(sz));
}

// ---------------- KNN ----------------
#define TPTS 2048
__global__ void knn_kernel(const float* __restrict__ qpos, const float* __restrict__ spos){
  __shared__ float sp[TPTS*3];
  int warp = threadIdx.x>>5, lane = threadIdx.x&31;
  int q = blockIdx.x*8 + warp;
  float qx=qpos[q*3+0], qy=qpos[q*3+1], qz=qpos[q*3+2];
  float qq = qx*qx+qy*qy+qz*qz;
  float bd[8]; int bi[8];
  #pragma unroll
  for (int j=0;j<8;j++){ bd[j]=3.0e38f; bi[j]=0x7fffffff; }
  for (int tile=0;tile<NPTS/TPTS;tile++){
    __syncthreads();
    for (int i=threadIdx.x;i<TPTS*3;i+=256) sp[i]=spos[tile*TPTS*3+i];
    __syncthreads();
    for (int p=lane;p<TPTS;p+=32){
      float sx=sp[3*p], sy=sp[3*p+1], sz=sp[3*p+2];
      float ss = sx*sx+sy*sy+sz*sz;
      float dot = qx*sx+qy*sy+qz*sz;
      float d2 = qq + ss - 2.f*dot;
      if (d2 < bd[7]){
        bd[7]=d2; bi[7]=tile*TPTS+p;
        for (int j=7;j>0;j--){
          if (bd[j]<bd[j-1]){ float td=bd[j];bd[j]=bd[j-1];bd[j-1]=td;
                              int ti=bi[j];bi[j]=bi[j-1];bi[j-1]=ti; }
          else break;
        }
      }
    }
  }
  for (int off=16;off;off>>=1){
    float od[8]; int oi[8];
    #pragma unroll
    for (int j=0;j<8;j++){
      od[j]=__shfl_xor_sync(0xffffffffu,bd[j],off);
      oi[j]=__shfl_xor_sync(0xffffffffu,bi[j],off);
    }
    float nd[8]; int ni[8]; int a=0,c=0;
    for (int t=0;t<8;t++){
      bool mine;
      if (a>=8) mine=false;
      else if (c>=8) mine=true;
      else mine = (bd[a]<od[c]) || (bd[a]==od[c] && bi[a]<=oi[c]);
      if (mine){ nd[t]=bd[a];ni[t]=bi[a];a++; } else { nd[t]=od[c];ni[t]=oi[c];c++; }
    }
    for (int j=0;j<8;j++){ bd[j]=nd[j]; bi[j]=ni[j]; }
  }
  if (lane==0){
    #pragma unroll
    for (int j=0;j<8;j++) g_idx[q*8+j]=bi[j];
  }
}

__global__ void inv_kernel(const int* __restrict__ order){
  int id=blockIdx.x*blockDim.x+threadIdx.x;
  if (id<2*QN) g_inv[(id/QN)*QN + order[id]] = id%QN;
}

// ---------------- tf32 GEMM, cp.async S-stage pipeline ----------------
template<int TBM_, int TBN_, int WM, int WN, int NTHR, int S>
__global__ void __launch_bounds__(NTHR) tgemm_kernel(
    const float* __restrict__ A, const float* __restrict__ B,
    const float* __restrict__ bias, const float* __restrict__ emul,
    float* __restrict__ Cmat, int M, int Nn, int Kk, int act){
  constexpr int MW = TBM_/WM;
  constexpr int MI = WM/16, NI = WN/8;
  constexpr int ROWS = TBM_+TBN_;
  constexpr int SLOTS = ROWS*4;
  constexpr int CNT = (SLOTS+NTHR-1)/NTHR;
  __shared__ float Sm[S][ROWS][20];
  int tid=threadIdx.x, warp=tid>>5, lane=tid&31;
  int wm=(warp%MW)*WM, wn=(warp/MW)*WN;
  int g=lane>>2, tig=lane&3;
  int row0=blockIdx.y*TBM_, col0=blockIdx.x*TBN_;

  float acc[MI][NI][4];
  #pragma unroll
  for (int mi=0;mi<MI;mi++)
    #pragma unroll
    for (int ni=0;ni<NI;ni++)
      #pragma unroll
      for (int r=0;r<4;r++) acc[mi][ni][r]=0.f;

  const float* gp[CNT]; uint32_t so[CNT]; bool val[CNT]; bool actv[CNT];
  #pragma unroll
  for (int i=0;i<CNT;i++){
    int idx=tid+i*NTHR;
    actv[i]=(idx<SLOTS);
    int idc = actv[i]? idx : 0;
    int r=idc>>2, c=(idc&3)<<2;
    if (r<TBM_){ gp[i]=A+(size_t)(row0+r)*Kk+c; val[i]=true; }
    else { int rb=r-TBM_; gp[i]=B+(size_t)(col0+rb)*Kk+c; val[i]=(col0+rb)<Nn; }
    so[i]=(uint32_t)__cvta_generic_to_shared(&Sm[0][r][c]);
  }
  constexpr uint32_t STGB=ROWS*20*4;
  auto issue=[&](int stage, int k0){
    #pragma unroll
    for (int i=0;i<CNT;i++)
      if (actv[i]) cpa16(so[i]+stage*STGB, gp[i]+k0, val[i]);
  };

  int KT=Kk>>4;
  #pragma unroll
  for (int s=0;s<S-1;s++){
    if (s<KT) issue(s, s<<4);
    asm volatile("cp.async.commit_group;" ::: "memory");
  }

  int stage=0;
  for (int kt=0;kt<KT;kt++){
    asm volatile("cp.async.wait_group %0;" :: "n"(S-2) : "memory");
    __syncthreads();
    int nt=kt+S-1;
    if (nt<KT) issue(nt%S, nt<<4);
    asm volatile("cp.async.commit_group;" ::: "memory");
    int p=stage;
    #pragma unroll
    for (int ks=0;ks<16;ks+=8){
      uint32_t af[MI][4], bf[NI][2];
      #pragma unroll
      for (int mi=0;mi<MI;mi++){
        int m=wm+mi*16+g;
        af[mi][0]=__float_as_uint(Sm[p][m  ][ks+tig  ]);
        af[mi][1]=__float_as_uint(Sm[p][m+8][ks+tig  ]);
        af[mi][2]=__float_as_uint(Sm[p][m  ][ks+tig+4]);
        af[mi][3]=__float_as_uint(Sm[p][m+8][ks+tig+4]);
      }
      #pragma unroll
      for (int ni=0;ni<NI;ni++){
        int n=TBM_+wn+ni*8+g;
        bf[ni][0]=__float_as_uint(Sm[p][n][ks+tig  ]);
        bf[ni][1]=__float_as_uint(Sm[p][n][ks+tig+4]);
      }
      #pragma unroll
      for (int mi=0;mi<MI;mi++)
        #pragma unroll
        for (int ni=0;ni<NI;ni++)
          mma_tf32(acc[mi][ni], af[mi][0],af[mi][1],af[mi][2],af[mi][3],
                   bf[ni][0],bf[ni][1]);
    }
    stage = (stage+1==S)? 0 : stage+1;
  }
  #pragma unroll
  for (int mi=0;mi<MI;mi++){
    int r=row0+wm+mi*16+g;
    #pragma unroll
    for (int ni=0;ni<NI;ni++){
      int c=col0+wn+ni*8+2*tig;
      if (c+1<Nn){
        #pragma unroll
        for (int half=0;half<2;half++){
          int rr=r+half*8;
          float v0=acc[mi][ni][half*2+0], v1=acc[mi][ni][half*2+1];
          if (emul){ v0*=emul[(size_t)rr*Nn+c]; v1*=emul[(size_t)rr*Nn+c+1]; }
          if (bias){ v0+=bias[c]; v1+=bias[c+1]; }
          if (act==1){
            v0=0.5f*v0*(1.f+erff(v0*0.70710678118654752f));
            v1=0.5f*v1*(1.f+erff(v1*0.70710678118654752f));
          }
          *(float2*)&Cmat[(size_t)rr*Nn+c]=make_float2(v0,v1);
        }
      }
    }
  }
}

// ---------------- mixbar: warp per query ----------------
__global__ void mixbar2_kernel(const float* __restrict__ wk, const float* __restrict__ wb,
                               const float* __restrict__ feats){
  int warp=threadIdx.x>>5, lane=threadIdx.x&31;
  int q=blockIdx.x*8+warp;
  const float4* q4=(const float4*)g_q;
  float4 qa=q4[q*64+lane], qb=q4[q*64+32+lane];
  const float4* w4=(const float4*)wk;
  float logit[8];
  #pragma unroll
  for (int k=0;k<8;k++){
    float4 wa=w4[k*64+lane], wb4=w4[k*64+32+lane];
    float p=qa.x*wa.x+qa.y*wa.y+qa.z*wa.z+qa.w*wa.w
           +qb.x*wb4.x+qb.y*wb4.y+qb.z*wb4.z+qb.w*wb4.w;
    logit[k]=warpSum(p)+wb[k];
  }
  float m=logit[0];
  #pragma unroll
  for (int k=1;k<8;k++) m=fmaxf(m,logit[k]);
  float s=0.f; float kw[8];
  #pragma unroll
  for (int k=0;k<8;k++){ kw[k]=expf(logit[k]-m); s+=kw[k]; }
  float inv=1.f/s;
  const float4* f4=(const float4*)feats;
  float4 acc0=make_float4(0,0,0,0), acc1=make_float4(0,0,0,0);
  #pragma unroll
  for (int k=0;k<8;k++){
    float w=kw[k]*inv;
    int idx=g_idx[q*8+k];
    float4 fa=f4[(size_t)idx*64+lane], fb=f4[(size_t)idx*64+32+lane];
    acc0.x+=w*fa.x; acc0.y+=w*fa.y; acc0.z+=w*fa.z; acc0.w+=w*fa.w;
    acc1.x+=w*fb.x; acc1.y+=w*fb.y; acc1.z+=w*fb.z; acc1.w+=w*fb.w;
  }
  float4* o4=(float4*)g_fbar;
  o4[q*64+lane]=acc0; o4[q*64+32+lane]=acc1;
}

// ---------------- warp-per-row LayerNorm: out = LN(a + b) ----------------
__global__ void lnw_kernel(float* __restrict__ out, const float* __restrict__ a,
                           const float* __restrict__ b){
  int row=blockIdx.x*8 + (threadIdx.x>>5), lane=threadIdx.x&31;
  const float4* a4=(const float4*)a; const float4* b4=(const float4*)b;
  float4 v0=a4[row*64+lane], v1=a4[row*64+32+lane];
  float4 w0=b4[row*64+lane], w1=b4[row*64+32+lane];
  v0.x+=w0.x;v0.y+=w0.y;v0.z+=w0.z;v0.w+=w0.w;
  v1.x+=w1.x;v1.y+=w1.y;v1.z+=w1.z;v1.w+=w1.w;
  float s=warpSum(v0.x+v0.y+v0.z+v0.w+v1.x+v1.y+v1.z+v1.w);
  float mean=s*(1.f/DM);
  float d0x=v0.x-mean,d0y=v0.y-mean,d0z=v0.z-mean,d0w=v0.w-mean;
  float d1x=v1.x-mean,d1y=v1.y-mean,d1z=v1.z-mean,d1w=v1.w-mean;
  float vs=warpSum(d0x*d0x+d0y*d0y+d0z*d0z+d0w*d0w+d1x*d1x+d1y*d1y+d1z*d1z+d1w*d1w);
  float r=rsqrtf(vs*(1.f/DM)+1e-5f);
  float4* o4=(float4*)out;
  o4[row*64+lane]   =make_float4(d0x*r,d0y*r,d0z*r,d0w*r);
  o4[row*64+32+lane]=make_float4(d1x*r,d1y*r,d1z*r,d1w*r);
}

// ---------------- warp-per-row LN + serialize ----------------
__global__ void lnserw_kernel(const int* __restrict__ order){
  int row=blockIdx.x*8 + (threadIdx.x>>5), lane=threadIdx.x&31;
  int src=order[row];
  const float4* a4=(const float4*)g_x;
  float4 v0=a4[src*64+lane], v1=a4[src*64+32+lane];
  float s=warpSum(v0.x+v0.y+v0.z+v0.w+v1.x+v1.y+v1.z+v1.w);
  float mean=s*(1.f/DM);
  float d0x=v0.x-mean,d0y=v0.y-mean,d0z=v0.z-mean,d0w=v0.w-mean;
  float d1x=v1.x-mean,d1y=v1.y-mean,d1z=v1.z-mean,d1w=v1.w-mean;
  float vs=warpSum(d0x*d0x+d0y*d0y+d0z*d0z+d0w*d0w+d1x*d1x+d1y*d1y+d1z*d1z+d1w*d1w);
  float r=rsqrtf(vs*(1.f/DM)+1e-5f);
  float4* o4=(float4*)g_xs;
  o4[row*64+lane]   =make_float4(d0x*r,d0y*r,d0z*r,d0w*r);
  o4[row*64+32+lane]=make_float4(d1x*r,d1y*r,d1z*r,d1w*r);
}

// ---------------- conv + silu: thread = (b, c4, 8 timesteps) ----------------
__global__ void conv8_kernel(const float* __restrict__ wconv, const float* __restrict__ bconv){
  int id=blockIdx.x*blockDim.x+threadIdx.x;
  int c4=id%160; int t8=(id/160)%(QN/8); int b=id/(160*(QN/8));
  int t0=t8*8;
  const float4* bc4=(const float4*)bconv;
  float4 bias=bc4[c4];
  const float4* w4=(const float4*)wconv;
  float4 w0=w4[c4*4+0], w1=w4[c4*4+1], w2=w4[c4*4+2], w3=w4[c4*4+3];
  const float4* p4=(const float4*)g_proj;
  float4 xv[11];
  #pragma unroll
  for (int i=0;i<11;i++){
    int tt=t0-3+i;
    xv[i] = (tt>=0)? p4[(size_t)(b*QN+tt)*(NPROJN/4) + DINN/4 + c4]
                   : make_float4(0.f,0.f,0.f,0.f);
  }
  float4* ob=(float4*)g_xbc;
  #pragma unroll
  for (int u=0;u<8;u++){
    float4 acc=bias;
    #pragma unroll
    for (int j=0;j<4;j++){
      float4 x=xv[u+j];
      acc.x+=x.x*(&w0.x)[j]; acc.y+=x.y*(&w1.x)[j];
      acc.z+=x.z*(&w2.x)[j]; acc.w+=x.w*(&w3.x)[j];
    }
    acc.x*=sigmoidf_(acc.x); acc.y*=sigmoidf_(acc.y);
    acc.z*=sigmoidf_(acc.z); acc.w*=sigmoidf_(acc.w);
    ob[(size_t)(b*QN+t0+u)*160 + c4]=acc;
  }
}

// ---------------- chunkH with fused dt/La scan (R8 scalar version) ----------------
__global__ void chunkH_kernel(const float* __restrict__ alog, const float* __restrict__ dtb){
  __shared__ float Xs[CSZ][HDIM], Bw[CSZ][STATE+1];
  __shared__ float La[CSZ], wv[CSZ];
  int bid=blockIdx.x;
  int c=bid%NCH, h=(bid/NCH)%NH, b=bid/(NCH*NH);
  int tid=threadIdx.x;
  int r0=b*QN + c*CSZ;
  float dtloc=0.f;
  if (tid<CSZ){
    int row=r0+tid;
    float raw = g_proj[(size_t)row*NPROJN + DINN+CONVN + h] + dtb[h];
    dtloc = raw>20.f? raw : log1pf(expf(raw));
    g_dts[row*NH+h]=dtloc;
    float A=-expf(alog[h]);
    La[tid]=dtloc*A;
  }
  __syncthreads();
  for (int o=1;o<CSZ;o<<=1){
    float v=0.f;
    if (tid<CSZ && tid>=o) v=La[tid-o];
    __syncthreads();
    if (tid<CSZ) La[tid]+=v;
    __syncthreads();
  }
  if (tid<CSZ) g_Las[(r0+tid)*NH+h]=La[tid];
  __syncthreads();
  if (tid<CSZ) wv[tid]=expf(La[CSZ-1]-La[tid])*dtloc;
  __syncthreads();
  for (int i=tid;i<CSZ*STATE;i+=256){
    int s=i>>6, k=i&63;
    const float* xr=&g_xbc[(size_t)(r0+s)*CONVN];
    Xs[s][k]=xr[h*HDIM+k];
    Bw[s][k]=xr[DINN+k]*wv[s];
  }
  __syncthreads();
  int hb=(tid>>4)<<2, sb=(tid&15)<<2;
  float acc[4][4];
  #pragma unroll
  for (int i=0;i<4;i++){ acc[i][0]=0;acc[i][1]=0;acc[i][2]=0;acc[i][3]=0; }
  for (int s=0;s<CSZ;s++){
    float xv[4], bv[4];
    #pragma unroll
    for (int i=0;i<4;i++) xv[i]=Xs[s][hb+i];
    #pragma unroll
    for (int j=0;j<4;j++) bv[j]=Bw[s][sb+j];
    #pragma unroll
    for (int i=0;i<4;i++)
      #pragma unroll
      for (int j=0;j<4;j++) acc[i][j]+=xv[i]*bv[j];
  }
  float* Hg=&g_Hc[(size_t)bid*HDIM*STATE];
  #pragma unroll
  for (int i=0;i<4;i++)
    #pragma unroll
    for (int j=0;j<4;j++)
      Hg[(hb+i)*STATE + sb+j]=acc[i][j];
}

// ---------------- carry: 128 blocks ----------------
__global__ void carry_kernel(){
  int bh=blockIdx.x>>3;
  int off=(blockIdx.x&7)*512 + threadIdx.x;
  int b=bh>>3, h=bh&7;
  size_t base0=(size_t)(bh*NCH)*HDIM*STATE;
  float hr=0.f;
  float nxt=g_Hc[base0+off];
  for (int c=0;c<NCH;c++){
    float Lend=g_Las[(b*QN + c*CSZ + CSZ-1)*NH + h];
    float f=expf(Lend);
    float cur=nxt;
    if (c+1<NCH) nxt=g_Hc[base0+(size_t)(c+1)*HDIM*STATE+off];
    g_Hin[base0+(size_t)c*HDIM*STATE+off]=hr;
    hr=f*hr+cur;
  }
}

// ---------------- fully fused P + y_intra + y_inter (R8 scalar version) ----------------
__global__ void pyfull_kernel(const float* __restrict__ Dh){
  __shared__ float S1[CSZ][STATE+1];
  __shared__ float S2[CSZ][STATE+1];
  __shared__ float La[CSZ], dtv[CSZ];
  int bid=blockIdx.x;
  int c=bid%NCH, h=(bid/NCH)%NH, b=bid/(NCH*NH);
  int tid=threadIdx.x;
  int r0=b*QN + c*CSZ;
  if (tid<CSZ){ La[tid]=g_Las[(r0+tid)*NH+h]; dtv[tid]=g_dts[(r0+tid)*NH+h]; }
  for (int i=tid;i<CSZ*STATE;i+=256){
    int s=i>>6, st=i&63;
    const float* xr=&g_xbc[(size_t)(r0+s)*CONVN];
    S1[s][st]=xr[DINN+st];
    S2[s][st]=xr[DINN+STATE+st];
  }
  __syncthreads();
  int tb=(tid>>4)<<2, sb=(tid&15)<<2;
  float acc[4][4];
  #pragma unroll
  for (int i=0;i<4;i++){ acc[i][0]=0;acc[i][1]=0;acc[i][2]=0;acc[i][3]=0; }
  for (int k=0;k<STATE;k++){
    float cv[4], bv[4];
    #pragma unroll
    for (int i=0;i<4;i++) cv[i]=S2[tb+i][k];
    #pragma unroll
    for (int j=0;j<4;j++) bv[j]=S1[sb+j][k];
    #pragma unroll
    for (int i=0;i<4;i++)
      #pragma unroll
      for (int j=0;j<4;j++) acc[i][j]+=cv[i]*bv[j];
  }
  float Pv[4][4];
  #pragma unroll
  for (int i=0;i<4;i++){
    int t=tb+i;
    #pragma unroll
    for (int j=0;j<4;j++){
      int s=sb+j;
      Pv[i][j]=(s<=t)? expf(La[t]-La[s])*dtv[s]*acc[i][j] : 0.f;
    }
  }
  __syncthreads();
  const float* Hg=&g_Hin[(size_t)bid*HDIM*STATE];
  for (int i=tid;i<HDIM*STATE;i+=256) S1[i>>6][i&63]=Hg[i];
  __syncthreads();
  float y2[4][4];
  #pragma unroll
  for (int i=0;i<4;i++){ y2[i][0]=0;y2[i][1]=0;y2[i][2]=0;y2[i][3]=0; }
  for (int k=0;k<STATE;k++){
    float cv[4], hv[4];
    #pragma unroll
    for (int i=0;i<4;i++) cv[i]=S2[tb+i][k];
    #pragma unroll
    for (int j=0;j<4;j++) hv[j]=S1[sb+j][k];
    #pragma unroll
    for (int i=0;i<4;i++)
      #pragma unroll
      for (int j=0;j<4;j++) y2[i][j]+=cv[i]*hv[j];
  }
  __syncthreads();
  #pragma unroll
  for (int i=0;i<4;i++)
    #pragma unroll
    for (int j=0;j<4;j++) S2[tb+i][sb+j]=Pv[i][j];
  for (int i=tid;i<CSZ*HDIM;i+=256){
    int s=i>>6,k=i&63;
    S1[s][k]=g_xbc[(size_t)(r0+s)*CONVN + h*HDIM + k];
  }
  __syncthreads();
  int hb=sb;
  float y1[4][4];
  #pragma unroll
  for (int i=0;i<4;i++){ y1[i][0]=0;y1[i][1]=0;y1[i][2]=0;y1[i][3]=0; }
  for (int s=0;s<CSZ;s++){
    float pv[4], xv[4];
    #pragma unroll
    for (int i=0;i<4;i++) pv[i]=S2[tb+i][s];
    #pragma unroll
    for (int j=0;j<4;j++) xv[j]=S1[s][hb+j];
    #pragma unroll
    for (int i=0;i<4;i++)
      #pragma unroll
      for (int j=0;j<4;j++) y1[i][j]+=pv[i]*xv[j];
  }
  float dh=Dh[h];
  #pragma unroll
  for (int i=0;i<4;i++){
    int t=tb+i;
    float f=expf(La[t]);
    #pragma unroll
    for (int j=0;j<4;j++)
      g_y[(size_t)(r0+t)*DINN + h*HDIM + hb+j] = y1[i][j] + dh*S1[t][hb+j] + f*y2[i][j];
  }
}

// ---------------- warp-per-row gated RMSNorm over 512 ----------------
__global__ void gate_rmsw_kernel(const float* __restrict__ rmsw){
  int row=blockIdx.x*8 + (threadIdx.x>>5), lane=threadIdx.x&31;
  const float4* y4=(const float4*)g_y;
  const float4* p4=(const float4*)g_proj;
  const float4* w4=(const float4*)rmsw;
  float4 gg[4];
  float ssum=0.f;
  #pragma unroll
  for (int i=0;i<4;i++){
    float4 y=y4[(size_t)row*128 + i*32 + lane];
    float4 z=p4[(size_t)row*(NPROJN/4) + i*32 + lane];
    gg[i].x=y.x*(z.x*sigmoidf_(z.x));
    gg[i].y=y.y*(z.y*sigmoidf_(z.y));
    gg[i].z=y.z*(z.z*sigmoidf_(z.z));
    gg[i].w=y.w*(z.w*sigmoidf_(z.w));
    ssum+=gg[i].x*gg[i].x+gg[i].y*gg[i].y+gg[i].z*gg[i].z+gg[i].w*gg[i].w;
  }
  ssum=warpSum(ssum);
  float r=rsqrtf(ssum*(1.f/DINN)+1e-5f);
  float4* o4=(float4*)g_gated;
  #pragma unroll
  for (int i=0;i<4;i++){
    float4 w=w4[i*32+lane];
    o4[(size_t)row*128 + i*32 + lane]=make_float4(gg[i].x*r*w.x, gg[i].y*r*w.y,
                                                  gg[i].z*r*w.z, gg[i].w*r*w.w);
  }
}

// ---------------- warp-per-row unsort + average + residual + LN ----------------
__global__ void merge_lnw_kernel(){
  int q=blockIdx.x*8 + (threadIdx.x>>5), lane=threadIdx.x&31;
  int i0=g_inv[q], i1=g_inv[QN+q];
  const float4* x4=(const float4*)g_x;
  const float4* s4=(const float4*)g_ssmout;
  float4 v0=x4[q*64+lane], v1=x4[q*64+32+lane];
  float4 a0=s4[(size_t)i0*64+lane], a1=s4[(size_t)i0*64+32+lane];
  float4 b0=s4[(size_t)(QN+i1)*64+lane], b1=s4[(size_t)(QN+i1)*64+32+lane];
  v0.x+=0.5f*(a0.x+b0.x); v0.y+=0.5f*(a0.y+b0.y);
  v0.z+=0.5f*(a0.z+b0.z); v0.w+=0.5f*(a0.w+b0.w);
  v1.x+=0.5f*(a1.x+b1.x); v1.y+=0.5f*(a1.y+b1.y);
  v1.z+=0.5f*(a1.z+b1.z); v1.w+=0.5f*(a1.w+b1.w);
  float s=warpSum(v0.x+v0.y+v0.z+v0.w+v1.x+v1.y+v1.z+v1.w);
  float mean=s*(1.f/DM);
  float d0x=v0.x-mean,d0y=v0.y-mean,d0z=v0.z-mean,d0w=v0.w-mean;
  float d1x=v1.x-mean,d1y=v1.y-mean,d1z=v1.z-mean,d1w=v1.w-mean;
  float vs=warpSum(d0x*d0x+d0y*d0y+d0z*d0z+d0w*d0w+d1x*d1x+d1y*d1y+d1z*d1z+d1w*d1w);
  float r=rsqrtf(vs*(1.f/DM)+1e-5f);
  float4* o4=(float4*)g_x;
  o4[q*64+lane]   =make_float4(d0x*r,d0y*r,d0z*r,d0w*r);
  o4[q*64+32+lane]=make_float4(d1x*r,d1y*r,d1z*r,d1w*r);
}

// =====================================================================
extern "C" void kernel_launch(void* const* d_in, const int* in_sizes, int n_in,
                              void* d_out, int out_size){
  const float* query      = (const float*)d_in[0];
  const float* query_pos  = (const float*)d_in[1];
  const float* inst_feats = (const float*)d_in[2];
  const float* sp_coords  = (const float*)d_in[3];
  const float* w_q  = (const float*)d_in[4];
  const float* w_v  = (const float*)d_in[5];
  const float* w_o  = (const float*)d_in[6];
  const float* w_k  = (const float*)d_in[7];
  const float* w_b  = (const float*)d_in[8];
  const float* Win  = (const float*)d_in[9];
  const float* Wconv= (const float*)d_in[10];
  const float* bconv= (const float*)d_in[11];
  const float* Alog = (const float*)d_in[12];
  const float* Dh   = (const float*)d_in[13];
  const float* dtb  = (const float*)d_in[14];
  const float* rmsw = (const float*)d_in[15];
  const float* Wout = (const float*)d_in[16];
  const float* fw1  = (const float*)d_in[17];
  const float* fb1  = (const float*)d_in[18];
  const float* fw2  = (const float*)d_in[19];
  const float* fb2  = (const float*)d_in[20];
  const int*   order= (const int*)  d_in[21];
  float* out = (float*)d_out;

  float *pq,*pfbar,*pvbar,*ptmp,*px,*pxs,*pproj,*pgated,*pssm,*pffnh;
  cudaGetSymbolAddress((void**)&pq,    g_q);
  cudaGetSymbolAddress((void**)&pfbar, g_fbar);
  cudaGetSymbolAddress((void**)&pvbar, g_vbar);
  cudaGetSymbolAddress((void**)&ptmp,  g_tmp);
  cudaGetSymbolAddress((void**)&px,    g_x);
  cudaGetSymbolAddress((void**)&pxs,   g_xs);
  cudaGetSymbolAddress((void**)&pproj, g_proj);
  cudaGetSymbolAddress((void**)&pgated,g_gated);
  cudaGetSymbolAddress((void**)&pssm,  g_ssmout);
  cudaGetSymbolAddress((void**)&pffnh, g_ffnh);

  auto gridS=[](int m,int n){ return dim3((unsigned)(n/32),(unsigned)(m/64)); };
  auto gridB=[](int m,int n){ return dim3((unsigned)((n+63)/64),(unsigned)(m/128)); };

  // --- stage 1 (launch #4 = wv GEMM for the profiler) ---
  knn_kernel<<<QN/8,256>>>(query_pos, sp_coords);
  tgemm_kernel<64,32,16,16,256,5><<<gridS(QN,DM),256>>>(query, w_q, nullptr, nullptr, pq, QN, DM, DM, 0);
  mixbar2_kernel<<<QN/8,256>>>(w_k, w_b, inst_feats);
  tgemm_kernel<64,32,16,16,256,5><<<gridS(QN,DM),256>>>(pfbar, w_v, nullptr, pq, pvbar, QN, DM, DM, 0);
  tgemm_kernel<64,32,16,16,256,5><<<gridS(QN,DM),256>>>(pvbar, w_o, nullptr, nullptr, ptmp, QN, DM, DM, 0);
  lnw_kernel<<<QN/8,256>>>(px, ptmp, query);
  inv_kernel<<<(2*QN+255)/256,256>>>(order);

  // --- stage 2: two Mamba2 layers ---
  for (int l=0;l<2;l++){
    lnserw_kernel<<<2*QN/8,256>>>(order);
    tgemm_kernel<128,64,32,32,256,3><<<gridB(2*QN,NPROJN),256>>>(pxs,
        Win + (size_t)l*NPROJN*DM, nullptr, nullptr, pproj, 2*QN, NPROJN, DM, 0);
    conv8_kernel<<<(2*(QN/8)*160)/256,256>>>(Wconv + (size_t)l*CONVN*4, bconv + (size_t)l*CONVN);
    chunkH_kernel<<<2*NH*NCH,256>>>(Alog + l*NH, dtb + l*NH);
    carry_kernel<<<2*NH*8,512>>>();
    pyfull_kernel<<<2*NH*NCH,256>>>(Dh + l*NH);
    gate_rmsw_kernel<<<2*QN/8,256>>>(rmsw + (size_t)l*DINN);
    tgemm_kernel<64,32,16,16,256,5><<<gridS(2*QN,DM),256>>>(pgated,
        Wout + (size_t)l*DM*DINN, nullptr, nullptr, pssm, 2*QN, DM, DINN, 0);
    merge_lnw_kernel<<<QN/8,256>>>();
  }

  // --- stage 3: FFN + final LN ---
  tgemm_kernel<128,64,32,32,256,3><<<gridB(QN,HIDN),256>>>(px, fw1, fb1, nullptr, pffnh, QN, HIDN, DM, 1);
  tgemm_kernel<64,32,16,16,256,5><<<gridS(QN,DM),256>>>(pffnh, fw2, fb2, nullptr, ptmp, QN, DM, HIDN, 0);
  lnw_kernel<<<QN/8,256>>>(out, ptmp, px);
}

// round 11
// speedup vs baseline: 1.1705x; 1.0110x over previous
#include <cuda_runtime.h>
#include <math.h>
#include <stdint.h>

#define QN 2048
#define NPTS 32768
#define DM 256
#define KNN 8
#define NH 8
#define HDIM 64
#define STATE 64
#define DINN 512
#define CONVN 640
#define NPROJN 1160
#define HIDN 1024
#define CSZ 64
#define NCH 32

// ---------------- scratch ----------------
__device__ float g_q[QN*DM];
__device__ float g_fbar[QN*DM];
__device__ float g_vbar[QN*DM];
__device__ float g_x[QN*DM];
__device__ float g_tmp[QN*DM];
__device__ int   g_idx[QN*KNN];
__device__ int   g_inv[2*QN];
__device__ float g_xs[2*QN*DM];
__device__ float g_proj[2*QN*NPROJN];
__device__ float g_xbc[2*QN*CONVN];
__device__ float g_dts[2*QN*NH];
__device__ float g_Las[2*QN*NH];
__device__ float g_Hc[2*NH*NCH*HDIM*STATE];
__device__ float g_Hin[2*NH*NCH*HDIM*STATE];
__device__ float g_y[2*QN*DINN];
__device__ float g_gated[2*QN*DINN];
__device__ float g_ssmout[2*QN*DM];
__device__ float g_ffnh[QN*HIDN];

__device__ __forceinline__ float sigmoidf_(float x){ return 1.f/(1.f+expf(-x)); }
__device__ __forceinline__ float warpSum(float v){
  #pragma unroll
  for (int o=16;o;o>>=1) v += __shfl_xor_sync(0xffffffffu, v, o);
  return v;
}
__device__ __forceinline__ void mma_tf32(float* d, uint32_t a0,uint32_t a1,uint32_t a2,uint32_t a3,
                                         uint32_t b0,uint32_t b1){
  asm volatile(
    "mma.sync.aligned.m16n8k8.row.col.f32.tf32.tf32.f32 "
    "{%0,%1,%2,%3}, {%4,%5,%6,%7}, {%8,%9}, {%0,%1,%2,%3};"
    : "+f"(d[0]),"+f"(d[1]),"+f"(d[2]),"+f"(d[3])
    : "r"(a0),"r"(a1),"r"(a2),"r"(a3),"r"(b0),"r"(b1));
}
__device__ __forceinline__ void cpa16(uint32_t s, const float* g, bool v){
  int sz = v?16:0;
  asm volatile("cp.async.cg.shared.global [%0], [%1], 16, %2;" :: "r"(s), "l"(g), "r"(sz));
}

// ---------------- KNN (+ fused inv computation) ----------------
#define TPTS 2048
__global__ void knn_kernel(const float* __restrict__ qpos, const float* __restrict__ spos,
                           const int* __restrict__ order){
  __shared__ float sp[TPTS*3];
  // fused: inverse permutation (4096 entries over 256 blocks x 256 thr => blocks 0..15)
  {
    int id=blockIdx.x*256+threadIdx.x;
    if (id<2*QN) g_inv[(id/QN)*QN + order[id]] = id%QN;
  }
  int warp = threadIdx.x>>5, lane = threadIdx.x&31;
  int q = blockIdx.x*8 + warp;
  float qx=qpos[q*3+0], qy=qpos[q*3+1], qz=qpos[q*3+2];
  float qq = qx*qx+qy*qy+qz*qz;
  float bd[8]; int bi[8];
  #pragma unroll
  for (int j=0;j<8;j++){ bd[j]=3.0e38f; bi[j]=0x7fffffff; }
  for (int tile=0;tile<NPTS/TPTS;tile++){
    __syncthreads();
    for (int i=threadIdx.x;i<TPTS*3;i+=256) sp[i]=spos[tile*TPTS*3+i];
    __syncthreads();
    for (int p=lane;p<TPTS;p+=32){
      float sx=sp[3*p], sy=sp[3*p+1], sz=sp[3*p+2];
      float ss = sx*sx+sy*sy+sz*sz;
      float dot = qx*sx+qy*sy+qz*sz;
      float d2 = qq + ss - 2.f*dot;
      if (d2 < bd[7]){
        bd[7]=d2; bi[7]=tile*TPTS+p;
        for (int j=7;j>0;j--){
          if (bd[j]<bd[j-1]){ float td=bd[j];bd[j]=bd[j-1];bd[j-1]=td;
                              int ti=bi[j];bi[j]=bi[j-1];bi[j-1]=ti; }
          else break;
        }
      }
    }
  }
  for (int off=16;off;off>>=1){
    float od[8]; int oi[8];
    #pragma unroll
    for (int j=0;j<8;j++){
      od[j]=__shfl_xor_sync(0xffffffffu,bd[j],off);
      oi[j]=__shfl_xor_sync(0xffffffffu,bi[j],off);
    }
    float nd[8]; int ni[8]; int a=0,c=0;
    for (int t=0;t<8;t++){
      bool mine;
      if (a>=8) mine=false;
      else if (c>=8) mine=true;
      else mine = (bd[a]<od[c]) || (bd[a]==od[c] && bi[a]<=oi[c]);
      if (mine){ nd[t]=bd[a];ni[t]=bi[a];a++; } else { nd[t]=od[c];ni[t]=oi[c];c++; }
    }
    for (int j=0;j<8;j++){ bd[j]=nd[j]; bi[j]=ni[j]; }
  }
  if (lane==0){
    #pragma unroll
    for (int j=0;j<8;j++) g_idx[q*8+j]=bi[j];
  }
}

// ---------------- tf32 GEMM, cp.async S-stage + fragment double buffering ----------------
template<int TBM_, int TBN_, int WM, int WN, int NTHR, int S>
__global__ void __launch_bounds__(NTHR) tgemm_kernel(
    const float* __restrict__ A, const float* __restrict__ B,
    const float* __restrict__ bias, const float* __restrict__ emul,
    float* __restrict__ Cmat, int M, int Nn, int Kk, int act){
  constexpr int MW = TBM_/WM;
  constexpr int MI = WM/16, NI = WN/8;
  constexpr int ROWS = TBM_+TBN_;
  constexpr int SLOTS = ROWS*4;
  constexpr int CNT = (SLOTS+NTHR-1)/NTHR;
  __shared__ float Sm[S][ROWS][20];
  int tid=threadIdx.x, warp=tid>>5, lane=tid&31;
  int wm=(warp%MW)*WM, wn=(warp/MW)*WN;
  int g=lane>>2, tig=lane&3;
  int row0=blockIdx.y*TBM_, col0=blockIdx.x*TBN_;

  float acc[MI][NI][4];
  #pragma unroll
  for (int mi=0;mi<MI;mi++)
    #pragma unroll
    for (int ni=0;ni<NI;ni++)
      #pragma unroll
      for (int r=0;r<4;r++) acc[mi][ni][r]=0.f;

  const float* gp[CNT]; uint32_t so[CNT]; bool val[CNT]; bool actv[CNT];
  #pragma unroll
  for (int i=0;i<CNT;i++){
    int idx=tid+i*NTHR;
    actv[i]=(idx<SLOTS);
    int idc = actv[i]? idx : 0;
    int r=idc>>2, c=(idc&3)<<2;
    if (r<TBM_){ gp[i]=A+(size_t)(row0+r)*Kk+c; val[i]=true; }
    else { int rb=r-TBM_; gp[i]=B+(size_t)(col0+rb)*Kk+c; val[i]=(col0+rb)<Nn; }
    so[i]=(uint32_t)__cvta_generic_to_shared(&Sm[0][r][c]);
  }
  constexpr uint32_t STGB=ROWS*20*4;
  auto issue=[&](int stage, int k0){
    #pragma unroll
    for (int i=0;i<CNT;i++)
      if (actv[i]) cpa16(so[i]+stage*STGB, gp[i]+k0, val[i]);
  };

  int KT=Kk>>4;
  #pragma unroll
  for (int s=0;s<S-1;s++){
    if (s<KT) issue(s, s<<4);
    asm volatile("cp.async.commit_group;" ::: "memory");
  }

  int stage=0;
  for (int kt=0;kt<KT;kt++){
    asm volatile("cp.async.wait_group %0;" :: "n"(S-2) : "memory");
    __syncthreads();
    int p=stage;
    // fragment group 0 (ks=0)
    uint32_t af0[MI][4], bf0[NI][2];
    #pragma unroll
    for (int mi=0;mi<MI;mi++){
      int m=wm+mi*16+g;
      af0[mi][0]=__float_as_uint(Sm[p][m  ][tig  ]);
      af0[mi][1]=__float_as_uint(Sm[p][m+8][tig  ]);
      af0[mi][2]=__float_as_uint(Sm[p][m  ][tig+4]);
      af0[mi][3]=__float_as_uint(Sm[p][m+8][tig+4]);
    }
    #pragma unroll
    for (int ni=0;ni<NI;ni++){
      int n=TBM_+wn+ni*8+g;
      bf0[ni][0]=__float_as_uint(Sm[p][n][tig  ]);
      bf0[ni][1]=__float_as_uint(Sm[p][n][tig+4]);
    }
    // overlap: issue next tile's cp.async
    int nt=kt+S-1;
    if (nt<KT) issue(nt%S, nt<<4);
    asm volatile("cp.async.commit_group;" ::: "memory");
    // fragment group 1 (ks=8) — loads in flight while group-0 MMAs run
    uint32_t af1[MI][4], bf1[NI][2];
    #pragma unroll
    for (int mi=0;mi<MI;mi++){
      int m=wm+mi*16+g;
      af1[mi][0]=__float_as_uint(Sm[p][m  ][8+tig  ]);
      af1[mi][1]=__float_as_uint(Sm[p][m+8][8+tig  ]);
      af1[mi][2]=__float_as_uint(Sm[p][m  ][8+tig+4]);
      af1[mi][3]=__float_as_uint(Sm[p][m+8][8+tig+4]);
    }
    #pragma unroll
    for (int ni=0;ni<NI;ni++){
      int n=TBM_+wn+ni*8+g;
      bf1[ni][0]=__float_as_uint(Sm[p][n][8+tig  ]);
      bf1[ni][1]=__float_as_uint(Sm[p][n][8+tig+4]);
    }
    #pragma unroll
    for (int mi=0;mi<MI;mi++)
      #pragma unroll
      for (int ni=0;ni<NI;ni++)
        mma_tf32(acc[mi][ni], af0[mi][0],af0[mi][1],af0[mi][2],af0[mi][3],
                 bf0[ni][0],bf0[ni][1]);
    #pragma unroll
    for (int mi=0;mi<MI;mi++)
      #pragma unroll
      for (int ni=0;ni<NI;ni++)
        mma_tf32(acc[mi][ni], af1[mi][0],af1[mi][1],af1[mi][2],af1[mi][3],
                 bf1[ni][0],bf1[ni][1]);
    stage = (stage+1==S)? 0 : stage+1;
  }
  #pragma unroll
  for (int mi=0;mi<MI;mi++){
    int r=row0+wm+mi*16+g;
    #pragma unroll
    for (int ni=0;ni<NI;ni++){
      int c=col0+wn+ni*8+2*tig;
      if (c+1<Nn){
        #pragma unroll
        for (int half=0;half<2;half++){
          int rr=r+half*8;
          float v0=acc[mi][ni][half*2+0], v1=acc[mi][ni][half*2+1];
          if (emul){ v0*=emul[(size_t)rr*Nn+c]; v1*=emul[(size_t)rr*Nn+c+1]; }
          if (bias){ v0+=bias[c]; v1+=bias[c+1]; }
          if (act==1){
            v0=0.5f*v0*(1.f+erff(v0*0.70710678118654752f));
            v1=0.5f*v1*(1.f+erff(v1*0.70710678118654752f));
          }
          *(float2*)&Cmat[(size_t)rr*Nn+c]=make_float2(v0,v1);
        }
      }
    }
  }
}

// ---------------- mixbar: warp per query ----------------
__global__ void mixbar2_kernel(const float* __restrict__ wk, const float* __restrict__ wb,
                               const float* __restrict__ feats){
  int warp=threadIdx.x>>5, lane=threadIdx.x&31;
  int q=blockIdx.x*8+warp;
  const float4* q4=(const float4*)g_q;
  float4 qa=q4[q*64+lane], qb=q4[q*64+32+lane];
  const float4* w4=(const float4*)wk;
  float logit[8];
  #pragma unroll
  for (int k=0;k<8;k++){
    float4 wa=w4[k*64+lane], wb4=w4[k*64+32+lane];
    float p=qa.x*wa.x+qa.y*wa.y+qa.z*wa.z+qa.w*wa.w
           +qb.x*wb4.x+qb.y*wb4.y+qb.z*wb4.z+qb.w*wb4.w;
    logit[k]=warpSum(p)+wb[k];
  }
  float m=logit[0];
  #pragma unroll
  for (int k=1;k<8;k++) m=fmaxf(m,logit[k]);
  float s=0.f; float kw[8];
  #pragma unroll
  for (int k=0;k<8;k++){ kw[k]=expf(logit[k]-m); s+=kw[k]; }
  float inv=1.f/s;
  const float4* f4=(const float4*)feats;
  float4 acc0=make_float4(0,0,0,0), acc1=make_float4(0,0,0,0);
  #pragma unroll
  for (int k=0;k<8;k++){
    float w=kw[k]*inv;
    int idx=g_idx[q*8+k];
    float4 fa=f4[(size_t)idx*64+lane], fb=f4[(size_t)idx*64+32+lane];
    acc0.x+=w*fa.x; acc0.y+=w*fa.y; acc0.z+=w*fa.z; acc0.w+=w*fa.w;
    acc1.x+=w*fb.x; acc1.y+=w*fb.y; acc1.z+=w*fb.z; acc1.w+=w*fb.w;
  }
  float4* o4=(float4*)g_fbar;
  o4[q*64+lane]=acc0; o4[q*64+32+lane]=acc1;
}

// ---------------- warp-per-row LayerNorm: out = LN(a + b) ----------------
__global__ void lnw_kernel(float* __restrict__ out, const float* __restrict__ a,
                           const float* __restrict__ b){
  int row=blockIdx.x*8 + (threadIdx.x>>5), lane=threadIdx.x&31;
  const float4* a4=(const float4*)a; const float4* b4=(const float4*)b;
  float4 v0=a4[row*64+lane], v1=a4[row*64+32+lane];
  float4 w0=b4[row*64+lane], w1=b4[row*64+32+lane];
  v0.x+=w0.x;v0.y+=w0.y;v0.z+=w0.z;v0.w+=w0.w;
  v1.x+=w1.x;v1.y+=w1.y;v1.z+=w1.z;v1.w+=w1.w;
  float s=warpSum(v0.x+v0.y+v0.z+v0.w+v1.x+v1.y+v1.z+v1.w);
  float mean=s*(1.f/DM);
  float d0x=v0.x-mean,d0y=v0.y-mean,d0z=v0.z-mean,d0w=v0.w-mean;
  float d1x=v1.x-mean,d1y=v1.y-mean,d1z=v1.z-mean,d1w=v1.w-mean;
  float vs=warpSum(d0x*d0x+d0y*d0y+d0z*d0z+d0w*d0w+d1x*d1x+d1y*d1y+d1z*d1z+d1w*d1w);
  float r=rsqrtf(vs*(1.f/DM)+1e-5f);
  float4* o4=(float4*)out;
  o4[row*64+lane]   =make_float4(d0x*r,d0y*r,d0z*r,d0w*r);
  o4[row*64+32+lane]=make_float4(d1x*r,d1y*r,d1z*r,d1w*r);
}

// ---------------- warp-per-row LN + serialize ----------------
__global__ void lnserw_kernel(const int* __restrict__ order){
  int row=blockIdx.x*8 + (threadIdx.x>>5), lane=threadIdx.x&31;
  int src=order[row];
  const float4* a4=(const float4*)g_x;
  float4 v0=a4[src*64+lane], v1=a4[src*64+32+lane];
  float s=warpSum(v0.x+v0.y+v0.z+v0.w+v1.x+v1.y+v1.z+v1.w);
  float mean=s*(1.f/DM);
  float d0x=v0.x-mean,d0y=v0.y-mean,d0z=v0.z-mean,d0w=v0.w-mean;
  float d1x=v1.x-mean,d1y=v1.y-mean,d1z=v1.z-mean,d1w=v1.w-mean;
  float vs=warpSum(d0x*d0x+d0y*d0y+d0z*d0z+d0w*d0w+d1x*d1x+d1y*d1y+d1z*d1z+d1w*d1w);
  float r=rsqrtf(vs*(1.f/DM)+1e-5f);
  float4* o4=(float4*)g_xs;
  o4[row*64+lane]   =make_float4(d0x*r,d0y*r,d0z*r,d0w*r);
  o4[row*64+32+lane]=make_float4(d1x*r,d1y*r,d1z*r,d1w*r);
}

// ---------------- conv + silu: thread = (b, c4, 8 timesteps) ----------------
__global__ void conv8_kernel(const float* __restrict__ wconv, const float* __restrict__ bconv){
  int id=blockIdx.x*blockDim.x+threadIdx.x;
  int c4=id%160; int t8=(id/160)%(QN/8); int b=id/(160*(QN/8));
  int t0=t8*8;
  const float4* bc4=(const float4*)bconv;
  float4 bias=bc4[c4];
  const float4* w4=(const float4*)wconv;
  float4 w0=w4[c4*4+0], w1=w4[c4*4+1], w2=w4[c4*4+2], w3=w4[c4*4+3];
  const float4* p4=(const float4*)g_proj;
  float4 xv[11];
  #pragma unroll
  for (int i=0;i<11;i++){
    int tt=t0-3+i;
    xv[i] = (tt>=0)? p4[(size_t)(b*QN+tt)*(NPROJN/4) + DINN/4 + c4]
                   : make_float4(0.f,0.f,0.f,0.f);
  }
  float4* ob=(float4*)g_xbc;
  #pragma unroll
  for (int u=0;u<8;u++){
    float4 acc=bias;
    #pragma unroll
    for (int j=0;j<4;j++){
      float4 x=xv[u+j];
      acc.x+=x.x*(&w0.x)[j]; acc.y+=x.y*(&w1.x)[j];
      acc.z+=x.z*(&w2.x)[j]; acc.w+=x.w*(&w3.x)[j];
    }
    acc.x*=sigmoidf_(acc.x); acc.y*=sigmoidf_(acc.y);
    acc.z*=sigmoidf_(acc.z); acc.w*=sigmoidf_(acc.w);
    ob[(size_t)(b*QN+t0+u)*160 + c4]=acc;
  }
}

// ---------------- chunkH with fused dt/La scan ----------------
__global__ void chunkH_kernel(const float* __restrict__ alog, const float* __restrict__ dtb){
  __shared__ float Xs[CSZ][HDIM], Bw[CSZ][STATE+1];
  __shared__ float La[CSZ], wv[CSZ];
  int bid=blockIdx.x;
  int c=bid%NCH, h=(bid/NCH)%NH, b=bid/(NCH*NH);
  int tid=threadIdx.x;
  int r0=b*QN + c*CSZ;
  float dtloc=0.f;
  if (tid<CSZ){
    int row=r0+tid;
    float raw = g_proj[(size_t)row*NPROJN + DINN+CONVN + h] + dtb[h];
    dtloc = raw>20.f? raw : log1pf(expf(raw));
    g_dts[row*NH+h]=dtloc;
    float A=-expf(alog[h]);
    La[tid]=dtloc*A;
  }
  __syncthreads();
  for (int o=1;o<CSZ;o<<=1){
    float v=0.f;
    if (tid<CSZ && tid>=o) v=La[tid-o];
    __syncthreads();
    if (tid<CSZ) La[tid]+=v;
    __syncthreads();
  }
  if (tid<CSZ) g_Las[(r0+tid)*NH+h]=La[tid];
  __syncthreads();
  if (tid<CSZ) wv[tid]=expf(La[CSZ-1]-La[tid])*dtloc;
  __syncthreads();
  for (int i=tid;i<CSZ*STATE;i+=256){
    int s=i>>6, k=i&63;
    const float* xr=&g_xbc[(size_t)(r0+s)*CONVN];
    Xs[s][k]=xr[h*HDIM+k];
    Bw[s][k]=xr[DINN+k]*wv[s];
  }
  __syncthreads();
  int hb=(tid>>4)<<2, sb=(tid&15)<<2;
  float acc[4][4];
  #pragma unroll
  for (int i=0;i<4;i++){ acc[i][0]=0;acc[i][1]=0;acc[i][2]=0;acc[i][3]=0; }
  for (int s=0;s<CSZ;s++){
    float xv[4], bv[4];
    #pragma unroll
    for (int i=0;i<4;i++) xv[i]=Xs[s][hb+i];
    #pragma unroll
    for (int j=0;j<4;j++) bv[j]=Bw[s][sb+j];
    #pragma unroll
    for (int i=0;i<4;i++)
      #pragma unroll
      for (int j=0;j<4;j++) acc[i][j]+=xv[i]*bv[j];
  }
  float* Hg=&g_Hc[(size_t)bid*HDIM*STATE];
  #pragma unroll
  for (int i=0;i<4;i++)
    #pragma unroll
    for (int j=0;j<4;j++)
      Hg[(hb+i)*STATE + sb+j]=acc[i][j];
}

// ---------------- carry: 128 blocks ----------------
__global__ void carry_kernel(){
  int bh=blockIdx.x>>3;
  int off=(blockIdx.x&7)*512 + threadIdx.x;
  int b=bh>>3, h=bh&7;
  size_t base0=(size_t)(bh*NCH)*HDIM*STATE;
  float hr=0.f;
  float nxt=g_Hc[base0+off];
  for (int c=0;c<NCH;c++){
    float Lend=g_Las[(b*QN + c*CSZ + CSZ-1)*NH + h];
    float f=expf(Lend);
    float cur=nxt;
    if (c+1<NCH) nxt=g_Hc[base0+(size_t)(c+1)*HDIM*STATE+off];
    g_Hin[base0+(size_t)c*HDIM*STATE+off]=hr;
    hr=f*hr+cur;
  }
}

// ---------------- fully fused P + y_intra + y_inter ----------------
__global__ void pyfull_kernel(const float* __restrict__ Dh){
  __shared__ float S1[CSZ][STATE+1];
  __shared__ float S2[CSZ][STATE+1];
  __shared__ float La[CSZ], dtv[CSZ];
  int bid=blockIdx.x;
  int c=bid%NCH, h=(bid/NCH)%NH, b=bid/(NCH*NH);
  int tid=threadIdx.x;
  int r0=b*QN + c*CSZ;
  if (tid<CSZ){ La[tid]=g_Las[(r0+tid)*NH+h]; dtv[tid]=g_dts[(r0+tid)*NH+h]; }
  for (int i=tid;i<CSZ*STATE;i+=256){
    int s=i>>6, st=i&63;
    const float* xr=&g_xbc[(size_t)(r0+s)*CONVN];
    S1[s][st]=xr[DINN+st];
    S2[s][st]=xr[DINN+STATE+st];
  }
  __syncthreads();
  int tb=(tid>>4)<<2, sb=(tid&15)<<2;
  float acc[4][4];
  #pragma unroll
  for (int i=0;i<4;i++){ acc[i][0]=0;acc[i][1]=0;acc[i][2]=0;acc[i][3]=0; }
  for (int k=0;k<STATE;k++){
    float cv[4], bv[4];
    #pragma unroll
    for (int i=0;i<4;i++) cv[i]=S2[tb+i][k];
    #pragma unroll
    for (int j=0;j<4;j++) bv[j]=S1[sb+j][k];
    #pragma unroll
    for (int i=0;i<4;i++)
      #pragma unroll
      for (int j=0;j<4;j++) acc[i][j]+=cv[i]*bv[j];
  }
  float Pv[4][4];
  #pragma unroll
  for (int i=0;i<4;i++){
    int t=tb+i;
    #pragma unroll
    for (int j=0;j<4;j++){
      int s=sb+j;
      Pv[i][j]=(s<=t)? expf(La[t]-La[s])*dtv[s]*acc[i][j] : 0.f;
    }
  }
  __syncthreads();
  const float* Hg=&g_Hin[(size_t)bid*HDIM*STATE];
  for (int i=tid;i<HDIM*STATE;i+=256) S1[i>>6][i&63]=Hg[i];
  __syncthreads();
  float y2[4][4];
  #pragma unroll
  for (int i=0;i<4;i++){ y2[i][0]=0;y2[i][1]=0;y2[i][2]=0;y2[i][3]=0; }
  for (int k=0;k<STATE;k++){
    float cv[4], hv[4];
    #pragma unroll
    for (int i=0;i<4;i++) cv[i]=S2[tb+i][k];
    #pragma unroll
    for (int j=0;j<4;j++) hv[j]=S1[sb+j][k];
    #pragma unroll
    for (int i=0;i<4;i++)
      #pragma unroll
      for (int j=0;j<4;j++) y2[i][j]+=cv[i]*hv[j];
  }
  __syncthreads();
  #pragma unroll
  for (int i=0;i<4;i++)
    #pragma unroll
    for (int j=0;j<4;j++) S2[tb+i][sb+j]=Pv[i][j];
  for (int i=tid;i<CSZ*HDIM;i+=256){
    int s=i>>6,k=i&63;
    S1[s][k]=g_xbc[(size_t)(r0+s)*CONVN + h*HDIM + k];
  }
  __syncthreads();
  int hb=sb;
  float y1[4][4];
  #pragma unroll
  for (int i=0;i<4;i++){ y1[i][0]=0;y1[i][1]=0;y1[i][2]=0;y1[i][3]=0; }
  for (int s=0;s<CSZ;s++){
    float pv[4], xv[4];
    #pragma unroll
    for (int i=0;i<4;i++) pv[i]=S2[tb+i][s];
    #pragma unroll
    for (int j=0;j<4;j++) xv[j]=S1[s][hb+j];
    #pragma unroll
    for (int i=0;i<4;i++)
      #pragma unroll
      for (int j=0;j<4;j++) y1[i][j]+=pv[i]*xv[j];
  }
  float dh=Dh[h];
  #pragma unroll
  for (int i=0;i<4;i++){
    int t=tb+i;
    float f=expf(La[t]);
    #pragma unroll
    for (int j=0;j<4;j++)
      g_y[(size_t)(r0+t)*DINN + h*HDIM + hb+j] = y1[i][j] + dh*S1[t][hb+j] + f*y2[i][j];
  }
}

// ---------------- warp-per-row gated RMSNorm over 512 ----------------
__global__ void gate_rmsw_kernel(const float* __restrict__ rmsw){
  int row=blockIdx.x*8 + (threadIdx.x>>5), lane=threadIdx.x&31;
  const float4* y4=(const float4*)g_y;
  const float4* p4=(const float4*)g_proj;
  const float4* w4=(const float4*)rmsw;
  float4 gg[4];
  float ssum=0.f;
  #pragma unroll
  for (int i=0;i<4;i++){
    float4 y=y4[(size_t)row*128 + i*32 + lane];
    float4 z=p4[(size_t)row*(NPROJN/4) + i*32 + lane];
    gg[i].x=y.x*(z.x*sigmoidf_(z.x));
    gg[i].y=y.y*(z.y*sigmoidf_(z.y));
    gg[i].z=y.z*(z.z*sigmoidf_(z.z));
    gg[i].w=y.w*(z.w*sigmoidf_(z.w));
    ssum+=gg[i].x*gg[i].x+gg[i].y*gg[i].y+gg[i].z*gg[i].z+gg[i].w*gg[i].w;
  }
  ssum=warpSum(ssum);
  float r=rsqrtf(ssum*(1.f/DINN)+1e-5f);
  float4* o4=(float4*)g_gated;
  #pragma unroll
  for (int i=0;i<4;i++){
    float4 w=w4[i*32+lane];
    o4[(size_t)row*128 + i*32 + lane]=make_float4(gg[i].x*r*w.x, gg[i].y*r*w.y,
                                                  gg[i].z*r*w.z, gg[i].w*r*w.w);
  }
}

// ---------------- warp-per-row unsort + average + residual + LN ----------------
__global__ void merge_lnw_kernel(){
  int q=blockIdx.x*8 + (threadIdx.x>>5), lane=threadIdx.x&31;
  int i0=g_inv[q], i1=g_inv[QN+q];
  const float4* x4=(const float4*)g_x;
  const float4* s4=(const float4*)g_ssmout;
  float4 v0=x4[q*64+lane], v1=x4[q*64+32+lane];
  float4 a0=s4[(size_t)i0*64+lane], a1=s4[(size_t)i0*64+32+lane];
  float4 b0=s4[(size_t)(QN+i1)*64+lane], b1=s4[(size_t)(QN+i1)*64+32+lane];
  v0.x+=0.5f*(a0.x+b0.x); v0.y+=0.5f*(a0.y+b0.y);
  v0.z+=0.5f*(a0.z+b0.z); v0.w+=0.5f*(a0.w+b0.w);
  v1.x+=0.5f*(a1.x+b1.x); v1.y+=0.5f*(a1.y+b1.y);
  v1.z+=0.5f*(a1.z+b1.z); v1.w+=0.5f*(a1.w+b1.w);
  float s=warpSum(v0.x+v0.y+v0.z+v0.w+v1.x+v1.y+v1.z+v1.w);
  float mean=s*(1.f/DM);
  float d0x=v0.x-mean,d0y=v0.y-mean,d0z=v0.z-mean,d0w=v0.w-mean;
  float d1x=v1.x-mean,d1y=v1.y-mean,d1z=v1.z-mean,d1w=v1.w-mean;
  float vs=warpSum(d0x*d0x+d0y*d0y+d0z*d0z+d0w*d0w+d1x*d1x+d1y*d1y+d1z*d1z+d1w*d1w);
  float r=rsqrtf(vs*(1.f/DM)+1e-5f);
  float4* o4=(float4*)g_x;
  o4[q*64+lane]   =make_float4(d0x*r,d0y*r,d0z*r,d0w*r);
  o4[q*64+32+lane]=make_float4(d1x*r,d1y*r,d1z*r,d1w*r);
}

// =====================================================================
extern "C" void kernel_launch(void* const* d_in, const int* in_sizes, int n_in,
                              void* d_out, int out_size){
  const float* query      = (const float*)d_in[0];
  const float* query_pos  = (const float*)d_in[1];
  const float* inst_feats = (const float*)d_in[2];
  const float* sp_coords  = (const float*)d_in[3];
  const float* w_q  = (const float*)d_in[4];
  const float* w_v  = (const float*)d_in[5];
  const float* w_o  = (const float*)d_in[6];
  const float* w_k  = (const float*)d_in[7];
  const float* w_b  = (const float*)d_in[8];
  const float* Win  = (const float*)d_in[9];
  const float* Wconv= (const float*)d_in[10];
  const float* bconv= (const float*)d_in[11];
  const float* Alog = (const float*)d_in[12];
  const float* Dh   = (const float*)d_in[13];
  const float* dtb  = (const float*)d_in[14];
  const float* rmsw = (const float*)d_in[15];
  const float* Wout = (const float*)d_in[16];
  const float* fw1  = (const float*)d_in[17];
  const float* fb1  = (const float*)d_in[18];
  const float* fw2  = (const float*)d_in[19];
  const float* fb2  = (const float*)d_in[20];
  const int*   order= (const int*)  d_in[21];
  float* out = (float*)d_out;

  float *pq,*pfbar,*pvbar,*ptmp,*px,*pxs,*pproj,*pgated,*pssm,*pffnh;
  cudaGetSymbolAddress((void**)&pq,    g_q);
  cudaGetSymbolAddress((void**)&pfbar, g_fbar);
  cudaGetSymbolAddress((void**)&pvbar, g_vbar);
  cudaGetSymbolAddress((void**)&ptmp,  g_tmp);
  cudaGetSymbolAddress((void**)&px,    g_x);
  cudaGetSymbolAddress((void**)&pxs,   g_xs);
  cudaGetSymbolAddress((void**)&pproj, g_proj);
  cudaGetSymbolAddress((void**)&pgated,g_gated);
  cudaGetSymbolAddress((void**)&pssm,  g_ssmout);
  cudaGetSymbolAddress((void**)&pffnh, g_ffnh);

  auto gridS=[](int m,int n){ return dim3((unsigned)(n/32),(unsigned)(m/64)); };
  auto gridB=[](int m,int n){ return dim3((unsigned)((n+63)/64),(unsigned)(m/128)); };

  // --- stage 1 (launch #4 = wv GEMM for the profiler) ---
  knn_kernel<<<QN/8,256>>>(query_pos, sp_coords, order);
  tgemm_kernel<64,32,16,16,256,5><<<gridS(QN,DM),256>>>(query, w_q, nullptr, nullptr, pq, QN, DM, DM, 0);
  mixbar2_kernel<<<QN/8,256>>>(w_k, w_b, inst_feats);
  tgemm_kernel<64,32,16,16,256,5><<<gridS(QN,DM),256>>>(pfbar, w_v, nullptr, pq, pvbar, QN, DM, DM, 0);
  tgemm_kernel<64,32,16,16,256,5><<<gridS(QN,DM),256>>>(pvbar, w_o, nullptr, nullptr, ptmp, QN, DM, DM, 0);
  lnw_kernel<<<QN/8,256>>>(px, ptmp, query);

  // --- stage 2: two Mamba2 layers ---
  for (int l=0;l<2;l++){
    lnserw_kernel<<<2*QN/8,256>>>(order);
    tgemm_kernel<128,64,32,32,256,3><<<gridB(2*QN,NPROJN),256>>>(pxs,
        Win + (size_t)l*NPROJN*DM, nullptr, nullptr, pproj, 2*QN, NPROJN, DM, 0);
    conv8_kernel<<<(2*(QN/8)*160)/256,256>>>(Wconv + (size_t)l*CONVN*4, bconv + (size_t)l*CONVN);
    chunkH_kernel<<<2*NH*NCH,256>>>(Alog + l*NH, dtb + l*NH);
    carry_kernel<<<2*NH*8,512>>>();
    pyfull_kernel<<<2*NH*NCH,256>>>(Dh + l*NH);
    gate_rmsw_kernel<<<2*QN/8,256>>>(rmsw + (size_t)l*DINN);
    tgemm_kernel<64,32,16,16,256,5><<<gridS(2*QN,DM),256>>>(pgated,
        Wout + (size_t)l*DM*DINN, nullptr, nullptr, pssm, 2*QN, DM, DINN, 0);
    merge_lnw_kernel<<<QN/8,256>>>();
  }

  // --- stage 3: FFN + final LN ---
  tgemm_kernel<128,64,32,32,256,3><<<gridB(QN,HIDN),256>>>(px, fw1, fb1, nullptr, pffnh, QN, HIDN, DM, 1);
  tgemm_kernel<64,32,16,16,256,5><<<gridS(QN,DM),256>>>(pffnh, fw2, fb2, nullptr, ptmp, QN, DM, HIDN, 0);
  lnw_kernel<<<QN/8,256>>>(out, ptmp, px);
}